// round 10
// baseline (speedup 1.0000x reference)
#include <cuda_runtime.h>
#include <cuda_bf16.h>
#include <mma.h>
#include <math.h>
#include <stdint.h>

using namespace nvcuda;

constexpr int SEQ   = 2048;
constexpr int HIDN  = 2048;
constexpr int NHEAD = 16;
constexpr int DHEAD = 128;
constexpr int QKVO  = 6144;
constexpr int KOFF  = 2048;
constexpr int VOFF  = 4096;

constexpr int BK   = 32;
constexpr int AKP  = 48;   // 96 B row stride (32B multiple)
constexpr int BNPb = 144;  // 288 B row stride

// fp32 intermediates (accumulator precision at stage boundaries)
__device__ float g_qkv[2][(size_t)SEQ * QKVO];
__device__ float g_scores[(size_t)NHEAD * SEQ * SEQ];
__device__ float g_attn[2][(size_t)SEQ * HIDN];
__device__ float g_cos[SEQ * DHEAD];
__device__ float g_sin[SEQ * DHEAD];

// pre-split bf16 hi/lo operand planes (GEMM inputs)
__device__ __nv_bfloat16 g_Xh[(size_t)SEQ * HIDN],      g_Xl[(size_t)SEQ * HIDN];
__device__ __nv_bfloat16 g_Wh[2][(size_t)HIDN * QKVO],  g_Wl[2][(size_t)HIDN * QKVO];
__device__ __nv_bfloat16 g_Woh[2][(size_t)HIDN * HIDN], g_Wol[2][(size_t)HIDN * HIDN];
__device__ __nv_bfloat16 g_qh[2][(size_t)SEQ * QKVO],   g_ql[2][(size_t)SEQ * QKVO];
__device__ __nv_bfloat16 g_Ph[(size_t)NHEAD * SEQ * SEQ], g_Pl[(size_t)NHEAD * SEQ * SEQ];
__device__ __nv_bfloat16 g_ah[2][(size_t)SEQ * HIDN],   g_al[2][(size_t)SEQ * HIDN];

using AFrag  = wmma::fragment<wmma::matrix_a, 16, 16, 16, __nv_bfloat16, wmma::row_major>;
using BFragR = wmma::fragment<wmma::matrix_b, 16, 16, 16, __nv_bfloat16, wmma::row_major>;
using BFragC = wmma::fragment<wmma::matrix_b, 16, 16, 16, __nv_bfloat16, wmma::col_major>;
using CFrag  = wmma::fragment<wmma::accumulator, 16, 16, 16, float>;

__device__ __forceinline__ void split1(float x, __nv_bfloat16& h, __nv_bfloat16& l) {
    h = __float2bfloat16_rn(x);
    l = __float2bfloat16_rn(x - __bfloat162float(h));
}

// ---------------- bf16 tile copy: gmem -> regs -> smem (256 threads) ----------------
// A-style tile: 128 rows x 32 cols (row stride AKP in smem)
__device__ __forceinline__ void ldA16(uint4 r[2], const __nv_bfloat16* g, int ld) {
    int t = threadIdx.x;
#pragma unroll
    for (int i = 0; i < 2; i++) {
        int idx = t + i * 256;
        int row = idx >> 2, col = (idx & 3) * 8;
        r[i] = *reinterpret_cast<const uint4*>(g + (size_t)row * ld + col);
    }
}
__device__ __forceinline__ void stA16(const uint4 r[2], __nv_bfloat16* s) {
    int t = threadIdx.x;
#pragma unroll
    for (int i = 0; i < 2; i++) {
        int idx = t + i * 256;
        int row = idx >> 2, col = (idx & 3) * 8;
        *reinterpret_cast<uint4*>(s + row * AKP + col) = r[i];
    }
}
// B-style tile: 32 rows x 128 cols (row stride BNPb in smem)
__device__ __forceinline__ void ldB16(uint4 r[2], const __nv_bfloat16* g, int ld) {
    int t = threadIdx.x;
#pragma unroll
    for (int i = 0; i < 2; i++) {
        int idx = t + i * 256;
        int row = idx >> 4, col = (idx & 15) * 8;
        r[i] = *reinterpret_cast<const uint4*>(g + (size_t)row * ld + col);
    }
}
__device__ __forceinline__ void stB16(const uint4 r[2], __nv_bfloat16* s) {
    int t = threadIdx.x;
#pragma unroll
    for (int i = 0; i < 2; i++) {
        int idx = t + i * 256;
        int row = idx >> 4, col = (idx & 15) * 8;
        *reinterpret_cast<uint4*>(s + row * BNPb + col) = r[i];
    }
}

// ---------------- bf16x3 mma core (unchanged layouts) ----------------
template <bool BT>
__device__ __forceinline__ void mma_bf16(const __nv_bfloat16* Ah, const __nv_bfloat16* Al,
                                         const __nv_bfloat16* Bh, const __nv_bfloat16* Bl,
                                         CFrag acc[4][2], int wm, int wn) {
#pragma unroll
    for (int kk = 0; kk < BK; kk += 16) {
        AFrag ah[4], al[4];
#pragma unroll
        for (int mi = 0; mi < 4; mi++) {
            wmma::load_matrix_sync(ah[mi], Ah + (wm * 64 + mi * 16) * AKP + kk, AKP);
            wmma::load_matrix_sync(al[mi], Al + (wm * 64 + mi * 16) * AKP + kk, AKP);
        }
#pragma unroll
        for (int ni = 0; ni < 2; ni++) {
            if constexpr (BT) {
                BFragC bh, bl;
                wmma::load_matrix_sync(bh, Bh + (wn * 32 + ni * 16) * AKP + kk, AKP);
                wmma::load_matrix_sync(bl, Bl + (wn * 32 + ni * 16) * AKP + kk, AKP);
#pragma unroll
                for (int mi = 0; mi < 4; mi++) {
                    wmma::mma_sync(acc[mi][ni], ah[mi], bh, acc[mi][ni]);
                    wmma::mma_sync(acc[mi][ni], al[mi], bh, acc[mi][ni]);
                    wmma::mma_sync(acc[mi][ni], ah[mi], bl, acc[mi][ni]);
                }
            } else {
                BFragR bh, bl;
                wmma::load_matrix_sync(bh, Bh + kk * BNPb + wn * 32 + ni * 16, BNPb);
                wmma::load_matrix_sync(bl, Bl + kk * BNPb + wn * 32 + ni * 16, BNPb);
#pragma unroll
                for (int mi = 0; mi < 4; mi++) {
                    wmma::mma_sync(acc[mi][ni], ah[mi], bh, acc[mi][ni]);
                    wmma::mma_sync(acc[mi][ni], al[mi], bh, acc[mi][ni]);
                    wmma::mma_sync(acc[mi][ni], ah[mi], bl, acc[mi][ni]);
                }
            }
        }
    }
}

__device__ __forceinline__ void epi_direct(CFrag acc[4][2], float* Cb, int ldc, int wm, int wn) {
#pragma unroll
    for (int mi = 0; mi < 4; mi++)
#pragma unroll
        for (int ni = 0; ni < 2; ni++)
            wmma::store_matrix_sync(Cb + (size_t)(wm * 64 + mi * 16) * ldc + wn * 32 + ni * 16,
                                    acc[mi][ni], ldc, wmma::mem_row_major);
}

// ---------------- kernel: elementwise fp32 -> (hi, lo) bf16 split ----------------
// which: 0=X, 1=Wqkv_r, 2=Wqkv_i, 3=Wo_r, 4=Wo_i, 5=attn(both planes, src ignored)
__global__ void __launch_bounds__(256)
k_split(const float* __restrict__ src, int which, int n) {
    __nv_bfloat16 *H, *L;
    switch (which) {
        case 0: H = g_Xh;     L = g_Xl;     break;
        case 1: H = g_Wh[0];  L = g_Wl[0];  break;
        case 2: H = g_Wh[1];  L = g_Wl[1];  break;
        case 3: H = g_Woh[0]; L = g_Wol[0]; break;
        case 4: H = g_Woh[1]; L = g_Wol[1]; break;
        default: H = g_ah[0]; L = g_al[0]; src = g_attn[0]; break;
    }
    int i = (blockIdx.x * 256 + threadIdx.x) * 4;
    if (i >= n) return;
    float4 v = *reinterpret_cast<const float4*>(src + i);
    __nv_bfloat16 h0, h1, h2, h3, l0, l1, l2, l3;
    split1(v.x, h0, l0); split1(v.y, h1, l1); split1(v.z, h2, l2); split1(v.w, h3, l3);
    *reinterpret_cast<__nv_bfloat162*>(H + i)     = __halves2bfloat162(h0, h1);
    *reinterpret_cast<__nv_bfloat162*>(H + i + 2) = __halves2bfloat162(h2, h3);
    *reinterpret_cast<__nv_bfloat162*>(L + i)     = __halves2bfloat162(l0, l1);
    *reinterpret_cast<__nv_bfloat162*>(L + i + 2) = __halves2bfloat162(l2, l3);
}

// ---------------- kernel 1: dual QKV GEMM (pre-split operands, double-buffered) ----------------
constexpr int ASZ = 128 * AKP;   // elems per A tile
constexpr int BSZ = 32 * BNPb;   // elems per B tile
constexpr int SMEM_NN = 2 * (2 * ASZ + 2 * BSZ) * 2;  // bytes: k_qkv/k_av/k_out
constexpr int SMEM_NT = 2 * (4 * ASZ) * 2;            // bytes: k_scores

__global__ void __launch_bounds__(256)
k_qkv() {
    extern __shared__ __align__(16) __nv_bfloat16 sm[];
    __nv_bfloat16 *Ah[2], *Al[2], *Bh[2], *Bl[2];
#pragma unroll
    for (int s = 0; s < 2; s++) {
        __nv_bfloat16* b = sm + s * (2 * ASZ + 2 * BSZ);
        Ah[s] = b; Al[s] = b + ASZ; Bh[s] = b + 2 * ASZ; Bl[s] = b + 2 * ASZ + BSZ;
    }
    int z = blockIdx.z;
    int i0 = blockIdx.y * 128, n0 = blockIdx.x * 128;
    int warp = threadIdx.x >> 5, wm = warp >> 2, wn = warp & 3;
    CFrag acc[4][2];
#pragma unroll
    for (int mi = 0; mi < 4; mi++)
#pragma unroll
        for (int ni = 0; ni < 2; ni++) wmma::fill_fragment(acc[mi][ni], 0.0f);

    const __nv_bfloat16* Agh = g_Xh + (size_t)i0 * HIDN;
    const __nv_bfloat16* Agl = g_Xl + (size_t)i0 * HIDN;
    const __nv_bfloat16* Bgh = g_Wh[z] + n0;
    const __nv_bfloat16* Bgl = g_Wl[z] + n0;

    uint4 rah[2], ral[2], rbh[2], rbl[2];
    ldA16(rah, Agh, HIDN); ldA16(ral, Agl, HIDN);
    ldB16(rbh, Bgh, QKVO); ldB16(rbl, Bgl, QKVO);
    stA16(rah, Ah[0]); stA16(ral, Al[0]); stB16(rbh, Bh[0]); stB16(rbl, Bl[0]);
    __syncthreads();

    const int kts = HIDN / BK;  // 64
    for (int kt = 0; kt < kts; ++kt) {
        int cur = kt & 1, nxt = cur ^ 1;
        if (kt + 1 < kts) {
            ldA16(rah, Agh + (kt + 1) * BK, HIDN);
            ldA16(ral, Agl + (kt + 1) * BK, HIDN);
            ldB16(rbh, Bgh + (size_t)(kt + 1) * BK * QKVO, QKVO);
            ldB16(rbl, Bgl + (size_t)(kt + 1) * BK * QKVO, QKVO);
        }
        mma_bf16<false>(Ah[cur], Al[cur], Bh[cur], Bl[cur], acc, wm, wn);
        if (kt + 1 < kts) {
            stA16(rah, Ah[nxt]); stA16(ral, Al[nxt]);
            stB16(rbh, Bh[nxt]); stB16(rbl, Bl[nxt]);
        }
        __syncthreads();
    }
    epi_direct(acc, g_qkv[z] + (size_t)i0 * QKVO + n0, QKVO, wm, wn);
}

// ---------------- kernel 2a: RoPE trig tables (fp64 angles) ----------------
__global__ void k_trig(const int* __restrict__ pos) {
    int idx = blockIdx.x * 256 + threadIdx.x;
    int s = idx >> 7, d = idx & 127;
    double invf = exp(-(double)d * (13.815510557964274 / 128.0));
    double th = (double)pos[s] * invf;
    double c, sn;
    sincos(th, &c, &sn);
    g_cos[idx] = (float)c;
    g_sin[idx] = (float)sn;
}

// ---------------- kernel 2b: bias + rotation by -theta; emit split bf16 ----------------
__global__ void __launch_bounds__(256)
k_biasrope(const float* __restrict__ br, const float* __restrict__ bi) {
    int idx = blockIdx.x * 256 + threadIdx.x;
    int s = idx / QKVO;
    int c = idx - s * QKVO;
    size_t o = (size_t)s * QKVO + c;
    float xr = g_qkv[0][o] + br[c];
    float xi = g_qkv[1][o] + bi[c];
    if (c < VOFF) {  // q or k: rotate by -theta (verified convention)
        int ti = (s << 7) | (c & 127);
        float cf = g_cos[ti], sf = g_sin[ti];
        float nr = xr * cf + xi * sf;
        float ni = -xr * sf + xi * cf;
        xr = nr; xi = ni;
    }
    __nv_bfloat16 h, l;
    split1(xr, h, l); g_qh[0][o] = h; g_ql[0][o] = l;
    split1(xi, h, l); g_qh[1][o] = h; g_ql[1][o] = l;
}

// ---------------- kernel 3: scores GEMM (NT, K=256, double-buffered) ----------------
__global__ void __launch_bounds__(256)
k_scores() {
    int h = blockIdx.z, i0 = blockIdx.y * 128, j0 = blockIdx.x * 128;
    if (j0 > i0) return;
    extern __shared__ __align__(16) __nv_bfloat16 sm[];
    __nv_bfloat16 *Ah[2], *Al[2], *Bh[2], *Bl[2];
#pragma unroll
    for (int s = 0; s < 2; s++) {
        __nv_bfloat16* b = sm + s * (4 * ASZ);
        Ah[s] = b; Al[s] = b + ASZ; Bh[s] = b + 2 * ASZ; Bl[s] = b + 3 * ASZ;
    }
    int warp = threadIdx.x >> 5, wm = warp >> 2, wn = warp & 3;
    CFrag acc[4][2];
#pragma unroll
    for (int mi = 0; mi < 4; mi++)
#pragma unroll
        for (int ni = 0; ni < 2; ni++) wmma::fill_fragment(acc[mi][ni], 0.0f);

    uint4 rah[2], ral[2], rbh[2], rbl[2];
    // tile bases for k-step kt: plane = kt>>2, col-chunk = (kt&3)*BK
    {
        const __nv_bfloat16* qh = g_qh[0] + (size_t)i0 * QKVO + h * DHEAD;
        const __nv_bfloat16* ql = g_ql[0] + (size_t)i0 * QKVO + h * DHEAD;
        const __nv_bfloat16* kh = g_qh[0] + (size_t)j0 * QKVO + KOFF + h * DHEAD;
        const __nv_bfloat16* kl = g_ql[0] + (size_t)j0 * QKVO + KOFF + h * DHEAD;
        ldA16(rah, qh, QKVO); ldA16(ral, ql, QKVO);
        ldA16(rbh, kh, QKVO); ldA16(rbl, kl, QKVO);
    }
    stA16(rah, Ah[0]); stA16(ral, Al[0]); stA16(rbh, Bh[0]); stA16(rbl, Bl[0]);
    __syncthreads();

    for (int kt = 0; kt < 8; ++kt) {
        int cur = kt & 1, nxt = cur ^ 1;
        if (kt + 1 < 8) {
            int nk = kt + 1, pl = nk >> 2, kc = (nk & 3) * BK;
            ldA16(rah, g_qh[pl] + (size_t)i0 * QKVO + h * DHEAD + kc, QKVO);
            ldA16(ral, g_ql[pl] + (size_t)i0 * QKVO + h * DHEAD + kc, QKVO);
            ldA16(rbh, g_qh[pl] + (size_t)j0 * QKVO + KOFF + h * DHEAD + kc, QKVO);
            ldA16(rbl, g_ql[pl] + (size_t)j0 * QKVO + KOFF + h * DHEAD + kc, QKVO);
        }
        mma_bf16<true>(Ah[cur], Al[cur], Bh[cur], Bl[cur], acc, wm, wn);
        if (kt + 1 < 8) {
            stA16(rah, Ah[nxt]); stA16(ral, Al[nxt]);
            stA16(rbh, Bh[nxt]); stA16(rbl, Bl[nxt]);
        }
        __syncthreads();
    }
    epi_direct(acc, g_scores + ((size_t)h * SEQ + i0) * SEQ + j0, SEQ, wm, wn);
}

// ---------------- kernel 4: softmax; emit split bf16 P; causal-aware IO ----------------
__device__ __forceinline__ void st4_split(__nv_bfloat16* H, __nv_bfloat16* L, int off,
                                          float a0, float a1, float a2, float a3) {
    __nv_bfloat16 h0, h1, h2, h3, l0, l1, l2, l3;
    split1(a0, h0, l0); split1(a1, h1, l1); split1(a2, h2, l2); split1(a3, h3, l3);
    *reinterpret_cast<__nv_bfloat162*>(H + off)     = __halves2bfloat162(h0, h1);
    *reinterpret_cast<__nv_bfloat162*>(H + off + 2) = __halves2bfloat162(h2, h3);
    *reinterpret_cast<__nv_bfloat162*>(L + off)     = __halves2bfloat162(l0, l1);
    *reinterpret_cast<__nv_bfloat162*>(L + off + 2) = __halves2bfloat162(l2, l3);
}

__global__ void __launch_bounds__(256)
k_softmax() {
    int bx = blockIdx.x;
    int r = bx & (SEQ - 1);
    const float* p = g_scores + (size_t)bx * SEQ;
    __nv_bfloat16* Ph = g_Ph + (size_t)bx * SEQ;
    __nv_bfloat16* Pl = g_Pl + (size_t)bx * SEQ;
    int tid = threadIdx.x;
    int c0 = tid * 4, c1 = 1024 + tid * 4;
    const float4* pv = reinterpret_cast<const float4*>(p);
    float4 v0 = (c0 <= r) ? pv[tid]       : make_float4(0.f, 0.f, 0.f, 0.f);
    float4 v1 = (c1 <= r) ? pv[tid + 256] : make_float4(0.f, 0.f, 0.f, 0.f);
    const float scale = 0.08838834764831845f;
    float a[8] = {v0.x, v0.y, v0.z, v0.w, v1.x, v1.y, v1.z, v1.w};
    int cols[8] = {c0, c0 + 1, c0 + 2, c0 + 3, c1, c1 + 1, c1 + 2, c1 + 3};

    float m = -3.4e38f;
#pragma unroll
    for (int j = 0; j < 8; j++)
        if (cols[j] <= r) { a[j] *= scale; m = fmaxf(m, a[j]); }

    __shared__ float red[8];
#pragma unroll
    for (int o = 16; o; o >>= 1) m = fmaxf(m, __shfl_xor_sync(0xffffffffu, m, o));
    if ((tid & 31) == 0) red[tid >> 5] = m;
    __syncthreads();
    float mb = fmaxf(fmaxf(fmaxf(red[0], red[1]), fmaxf(red[2], red[3])),
                     fmaxf(fmaxf(red[4], red[5]), fmaxf(red[6], red[7])));

    float s = 0.f;
#pragma unroll
    for (int j = 0; j < 8; j++) {
        a[j] = (cols[j] <= r) ? expf(a[j] - mb) : 0.f;
        s += a[j];
    }
#pragma unroll
    for (int o = 16; o; o >>= 1) s += __shfl_xor_sync(0xffffffffu, s, o);
    __syncthreads();
    if ((tid & 31) == 0) red[tid >> 5] = s;
    __syncthreads();
    float inv = 1.0f / (red[0] + red[1] + red[2] + red[3] + red[4] + red[5] + red[6] + red[7]);

    int bend = r | 127;  // end of this row's diagonal 128-block (k_av never reads past it)
    if (c0 <= bend) st4_split(Ph, Pl, c0, a[0] * inv, a[1] * inv, a[2] * inv, a[3] * inv);
    if (c1 <= bend) st4_split(Ph, Pl, c1, a[4] * inv, a[5] * inv, a[6] * inv, a[7] * inv);
}

// ---------------- kernel 5: attn @ V (double-buffered) ----------------
__global__ void __launch_bounds__(256)
k_av() {
    int bz = blockIdx.z;
    int h = bz >> 1, z = bz & 1;
    int i0 = blockIdx.y * 128;
    extern __shared__ __align__(16) __nv_bfloat16 sm[];
    __nv_bfloat16 *Ah[2], *Al[2], *Bh[2], *Bl[2];
#pragma unroll
    for (int s = 0; s < 2; s++) {
        __nv_bfloat16* b = sm + s * (2 * ASZ + 2 * BSZ);
        Ah[s] = b; Al[s] = b + ASZ; Bh[s] = b + 2 * ASZ; Bl[s] = b + 2 * ASZ + BSZ;
    }
    int warp = threadIdx.x >> 5, wm = warp >> 2, wn = warp & 3;
    CFrag acc[4][2];
#pragma unroll
    for (int mi = 0; mi < 4; mi++)
#pragma unroll
        for (int ni = 0; ni < 2; ni++) wmma::fill_fragment(acc[mi][ni], 0.0f);

    const __nv_bfloat16* Agh = g_Ph + (size_t)h * SEQ * SEQ + (size_t)i0 * SEQ;
    const __nv_bfloat16* Agl = g_Pl + (size_t)h * SEQ * SEQ + (size_t)i0 * SEQ;
    const __nv_bfloat16* Bgh = g_qh[z] + VOFF + h * DHEAD;
    const __nv_bfloat16* Bgl = g_ql[z] + VOFF + h * DHEAD;

    uint4 rah[2], ral[2], rbh[2], rbl[2];
    ldA16(rah, Agh, SEQ); ldA16(ral, Agl, SEQ);
    ldB16(rbh, Bgh, QKVO); ldB16(rbl, Bgl, QKVO);
    stA16(rah, Ah[0]); stA16(ral, Al[0]); stB16(rbh, Bh[0]); stB16(rbl, Bl[0]);
    __syncthreads();

    int ktiles = (i0 + 128) / BK;
    for (int kt = 0; kt < ktiles; ++kt) {
        int cur = kt & 1, nxt = cur ^ 1;
        if (kt + 1 < ktiles) {
            ldA16(rah, Agh + (kt + 1) * BK, SEQ);
            ldA16(ral, Agl + (kt + 1) * BK, SEQ);
            ldB16(rbh, Bgh + (size_t)(kt + 1) * BK * QKVO, QKVO);
            ldB16(rbl, Bgl + (size_t)(kt + 1) * BK * QKVO, QKVO);
        }
        mma_bf16<false>(Ah[cur], Al[cur], Bh[cur], Bl[cur], acc, wm, wn);
        if (kt + 1 < ktiles) {
            stA16(rah, Ah[nxt]); stA16(ral, Al[nxt]);
            stB16(rbh, Bh[nxt]); stB16(rbl, Bl[nxt]);
        }
        __syncthreads();
    }
    epi_direct(acc, g_attn[z] + (size_t)i0 * HIDN + h * DHEAD, HIDN, wm, wn);
}

// ---------------- kernel 6: output projections (double-buffered) ----------------
__global__ void __launch_bounds__(256)
k_out(float* __restrict__ out) {
    int z = blockIdx.z;
    int i0 = blockIdx.y * 128, n0 = blockIdx.x * 128;
    extern __shared__ __align__(16) __nv_bfloat16 sm[];
    __nv_bfloat16 *Ah[2], *Al[2], *Bh[2], *Bl[2];
#pragma unroll
    for (int s = 0; s < 2; s++) {
        __nv_bfloat16* b = sm + s * (2 * ASZ + 2 * BSZ);
        Ah[s] = b; Al[s] = b + ASZ; Bh[s] = b + 2 * ASZ; Bl[s] = b + 2 * ASZ + BSZ;
    }
    int warp = threadIdx.x >> 5, wm = warp >> 2, wn = warp & 3;
    CFrag acc[4][2];
#pragma unroll
    for (int mi = 0; mi < 4; mi++)
#pragma unroll
        for (int ni = 0; ni < 2; ni++) wmma::fill_fragment(acc[mi][ni], 0.0f);

    const __nv_bfloat16* Agh = g_ah[z] + (size_t)i0 * HIDN;
    const __nv_bfloat16* Agl = g_al[z] + (size_t)i0 * HIDN;
    const __nv_bfloat16* Bgh = g_Woh[z] + n0;
    const __nv_bfloat16* Bgl = g_Wol[z] + n0;

    uint4 rah[2], ral[2], rbh[2], rbl[2];
    ldA16(rah, Agh, HIDN); ldA16(ral, Agl, HIDN);
    ldB16(rbh, Bgh, HIDN); ldB16(rbl, Bgl, HIDN);
    stA16(rah, Ah[0]); stA16(ral, Al[0]); stB16(rbh, Bh[0]); stB16(rbl, Bl[0]);
    __syncthreads();

    const int kts = HIDN / BK;
    for (int kt = 0; kt < kts; ++kt) {
        int cur = kt & 1, nxt = cur ^ 1;
        if (kt + 1 < kts) {
            ldA16(rah, Agh + (kt + 1) * BK, HIDN);
            ldA16(ral, Agl + (kt + 1) * BK, HIDN);
            ldB16(rbh, Bgh + (size_t)(kt + 1) * BK * HIDN, HIDN);
            ldB16(rbl, Bgl + (size_t)(kt + 1) * BK * HIDN, HIDN);
        }
        mma_bf16<false>(Ah[cur], Al[cur], Bh[cur], Bl[cur], acc, wm, wn);
        if (kt + 1 < kts) {
            stA16(rah, Ah[nxt]); stA16(ral, Al[nxt]);
            stB16(rbh, Bh[nxt]); stB16(rbl, Bl[nxt]);
        }
        __syncthreads();
    }
    epi_direct(acc, out + (size_t)z * SEQ * HIDN + (size_t)i0 * HIDN + n0, HIDN, wm, wn);
}

// ---------------- launch ----------------
extern "C" void kernel_launch(void* const* d_in, const int* in_sizes, int n_in,
                              void* d_out, int out_size) {
    const float* hidden = (const float*)d_in[0];
    const int*   pos    = (const int*)d_in[1];
    const float* Wqkv_r = (const float*)d_in[2];
    const float* bqkv_r = (const float*)d_in[3];
    const float* Wqkv_i = (const float*)d_in[4];
    const float* bqkv_i = (const float*)d_in[5];
    const float* Wo_r   = (const float*)d_in[6];
    const float* Wo_i   = (const float*)d_in[7];
    float* out = (float*)d_out;

    cudaFuncSetAttribute(k_qkv,    cudaFuncAttributeMaxDynamicSharedMemorySize, SMEM_NN);
    cudaFuncSetAttribute(k_scores, cudaFuncAttributeMaxDynamicSharedMemorySize, SMEM_NT);
    cudaFuncSetAttribute(k_av,     cudaFuncAttributeMaxDynamicSharedMemorySize, SMEM_NN);
    cudaFuncSetAttribute(k_out,    cudaFuncAttributeMaxDynamicSharedMemorySize, SMEM_NN);

    dim3 blk(256);
    k_trig<<<(SEQ * DHEAD) / 256, blk>>>(pos);
    k_split<<<(SEQ * HIDN) / 1024, blk>>>(hidden, 0, SEQ * HIDN);
    k_split<<<(HIDN * QKVO) / 1024, blk>>>(Wqkv_r, 1, HIDN * QKVO);
    k_split<<<(HIDN * QKVO) / 1024, blk>>>(Wqkv_i, 2, HIDN * QKVO);
    k_split<<<(HIDN * HIDN) / 1024, blk>>>(Wo_r, 3, HIDN * HIDN);
    k_split<<<(HIDN * HIDN) / 1024, blk>>>(Wo_i, 4, HIDN * HIDN);
    k_qkv<<<dim3(QKVO / 128, SEQ / 128, 2), blk, SMEM_NN>>>();
    k_biasrope<<<(SEQ * QKVO) / 256, blk>>>(bqkv_r, bqkv_i);
    k_scores<<<dim3(SEQ / 128, SEQ / 128, NHEAD), blk, SMEM_NT>>>();
    k_softmax<<<NHEAD * SEQ, blk>>>();
    k_av<<<dim3(1, SEQ / 128, NHEAD * 2), blk, SMEM_NN>>>();
    k_split<<<(2 * SEQ * HIDN) / 1024, blk>>>(nullptr, 5, 2 * SEQ * HIDN);
    int zcount = (out_size >= 2 * SEQ * HIDN) ? 2 : 1;
    k_out<<<dim3(HIDN / 128, SEQ / 128, zcount), blk, SMEM_NN>>>(out);
}

// round 11
// speedup vs baseline: 1.1325x; 1.1325x over previous
#include <cuda_runtime.h>
#include <cuda_bf16.h>
#include <mma.h>
#include <math.h>
#include <stdint.h>

using namespace nvcuda;

constexpr int SEQ   = 2048;
constexpr int HIDN  = 2048;
constexpr int NHEAD = 16;
constexpr int DHEAD = 128;
constexpr int QKVO  = 6144;
constexpr int KOFF  = 2048;
constexpr int VOFF  = 4096;

constexpr int BK   = 32;
constexpr int AKP  = 48;   // 96 B row stride (32B multiple)
constexpr int BNPb = 144;  // 288 B row stride

// fp32 intermediates
__device__ float g_qkv[2][(size_t)SEQ * QKVO];
__device__ float g_scores[(size_t)NHEAD * SEQ * SEQ];
__device__ float g_attn[2][(size_t)SEQ * HIDN];
__device__ float g_cos[SEQ * DHEAD];
__device__ float g_sin[SEQ * DHEAD];

// pre-split bf16 hi/lo operand planes
__device__ __nv_bfloat16 g_Xh[(size_t)SEQ * HIDN],      g_Xl[(size_t)SEQ * HIDN];
__device__ __nv_bfloat16 g_Wh[2][(size_t)HIDN * QKVO],  g_Wl[2][(size_t)HIDN * QKVO];
__device__ __nv_bfloat16 g_Woh[2][(size_t)HIDN * HIDN], g_Wol[2][(size_t)HIDN * HIDN];
__device__ __nv_bfloat16 g_qh[2][(size_t)SEQ * QKVO],   g_ql[2][(size_t)SEQ * QKVO];
__device__ __nv_bfloat16 g_Ph[(size_t)NHEAD * SEQ * SEQ], g_Pl[(size_t)NHEAD * SEQ * SEQ];
__device__ __nv_bfloat16 g_ah[2][(size_t)SEQ * HIDN],   g_al[2][(size_t)SEQ * HIDN];

using AFrag  = wmma::fragment<wmma::matrix_a, 16, 16, 16, __nv_bfloat16, wmma::row_major>;
using BFragR = wmma::fragment<wmma::matrix_b, 16, 16, 16, __nv_bfloat16, wmma::row_major>;
using BFragC = wmma::fragment<wmma::matrix_b, 16, 16, 16, __nv_bfloat16, wmma::col_major>;
using CFrag  = wmma::fragment<wmma::accumulator, 16, 16, 16, float>;

__device__ __forceinline__ void split1(float x, __nv_bfloat16& h, __nv_bfloat16& l) {
    h = __float2bfloat16_rn(x);
    l = __float2bfloat16_rn(x - __bfloat162float(h));
}

// ---------------- bf16 tile copy helpers (256 threads, uint4) ----------------
__device__ __forceinline__ void ldA16(uint4 r[2], const __nv_bfloat16* g, int ld) {
    int t = threadIdx.x;
#pragma unroll
    for (int i = 0; i < 2; i++) {
        int idx = t + i * 256;
        int row = idx >> 2, col = (idx & 3) * 8;
        r[i] = *reinterpret_cast<const uint4*>(g + (size_t)row * ld + col);
    }
}
__device__ __forceinline__ void stA16(const uint4 r[2], __nv_bfloat16* s) {
    int t = threadIdx.x;
#pragma unroll
    for (int i = 0; i < 2; i++) {
        int idx = t + i * 256;
        int row = idx >> 2, col = (idx & 3) * 8;
        *reinterpret_cast<uint4*>(s + row * AKP + col) = r[i];
    }
}
__device__ __forceinline__ void ldB16(uint4 r[2], const __nv_bfloat16* g, int ld) {
    int t = threadIdx.x;
#pragma unroll
    for (int i = 0; i < 2; i++) {
        int idx = t + i * 256;
        int row = idx >> 4, col = (idx & 15) * 8;
        r[i] = *reinterpret_cast<const uint4*>(g + (size_t)row * ld + col);
    }
}
__device__ __forceinline__ void stB16(const uint4 r[2], __nv_bfloat16* s) {
    int t = threadIdx.x;
#pragma unroll
    for (int i = 0; i < 2; i++) {
        int idx = t + i * 256;
        int row = idx >> 4, col = (idx & 15) * 8;
        *reinterpret_cast<uint4*>(s + row * BNPb + col) = r[i];
    }
}

// ---------------- bf16x3 mma core ----------------
template <bool BT>
__device__ __forceinline__ void mma_bf16(const __nv_bfloat16* Ah, const __nv_bfloat16* Al,
                                         const __nv_bfloat16* Bh, const __nv_bfloat16* Bl,
                                         CFrag acc[4][2], int wm, int wn) {
#pragma unroll
    for (int kk = 0; kk < BK; kk += 16) {
        AFrag ah[4], al[4];
#pragma unroll
        for (int mi = 0; mi < 4; mi++) {
            wmma::load_matrix_sync(ah[mi], Ah + (wm * 64 + mi * 16) * AKP + kk, AKP);
            wmma::load_matrix_sync(al[mi], Al + (wm * 64 + mi * 16) * AKP + kk, AKP);
        }
#pragma unroll
        for (int ni = 0; ni < 2; ni++) {
            if constexpr (BT) {
                BFragC bh, bl;
                wmma::load_matrix_sync(bh, Bh + (wn * 32 + ni * 16) * AKP + kk, AKP);
                wmma::load_matrix_sync(bl, Bl + (wn * 32 + ni * 16) * AKP + kk, AKP);
#pragma unroll
                for (int mi = 0; mi < 4; mi++) {
                    wmma::mma_sync(acc[mi][ni], ah[mi], bh, acc[mi][ni]);
                    wmma::mma_sync(acc[mi][ni], al[mi], bh, acc[mi][ni]);
                    wmma::mma_sync(acc[mi][ni], ah[mi], bl, acc[mi][ni]);
                }
            } else {
                BFragR bh, bl;
                wmma::load_matrix_sync(bh, Bh + kk * BNPb + wn * 32 + ni * 16, BNPb);
                wmma::load_matrix_sync(bl, Bl + kk * BNPb + wn * 32 + ni * 16, BNPb);
#pragma unroll
                for (int mi = 0; mi < 4; mi++) {
                    wmma::mma_sync(acc[mi][ni], ah[mi], bh, acc[mi][ni]);
                    wmma::mma_sync(acc[mi][ni], al[mi], bh, acc[mi][ni]);
                    wmma::mma_sync(acc[mi][ni], ah[mi], bl, acc[mi][ni]);
                }
            }
        }
    }
}

__device__ __forceinline__ void epi_direct(CFrag acc[4][2], float* Cb, int ldc, int wm, int wn) {
#pragma unroll
    for (int mi = 0; mi < 4; mi++)
#pragma unroll
        for (int ni = 0; ni < 2; ni++)
            wmma::store_matrix_sync(Cb + (size_t)(wm * 64 + mi * 16) * ldc + wn * 32 + ni * 16,
                                    acc[mi][ni], ldc, wmma::mem_row_major);
}

// ---------------- elementwise fp32 -> (hi, lo) split ----------------
__global__ void __launch_bounds__(256)
k_split(const float* __restrict__ src, int which, int n) {
    __nv_bfloat16 *H, *L;
    switch (which) {
        case 0: H = g_Xh;     L = g_Xl;     break;
        case 1: H = g_Wh[0];  L = g_Wl[0];  break;
        case 2: H = g_Wh[1];  L = g_Wl[1];  break;
        case 3: H = g_Woh[0]; L = g_Wol[0]; break;
        case 4: H = g_Woh[1]; L = g_Wol[1]; break;
        default: H = g_ah[0]; L = g_al[0]; src = g_attn[0]; break;
    }
    int i = (blockIdx.x * 256 + threadIdx.x) * 4;
    if (i >= n) return;
    float4 v = *reinterpret_cast<const float4*>(src + i);
    __nv_bfloat16 h0, h1, h2, h3, l0, l1, l2, l3;
    split1(v.x, h0, l0); split1(v.y, h1, l1); split1(v.z, h2, l2); split1(v.w, h3, l3);
    *reinterpret_cast<__nv_bfloat162*>(H + i)     = __halves2bfloat162(h0, h1);
    *reinterpret_cast<__nv_bfloat162*>(H + i + 2) = __halves2bfloat162(h2, h3);
    *reinterpret_cast<__nv_bfloat162*>(L + i)     = __halves2bfloat162(l0, l1);
    *reinterpret_cast<__nv_bfloat162*>(L + i + 2) = __halves2bfloat162(l2, l3);
}

constexpr int ASZ = 128 * AKP;   // 6144 elems
constexpr int BSZ = 32 * BNPb;   // 4608 elems
constexpr int SMEM_NN = (2 * ASZ + 2 * BSZ) * 2;  // 43008 B
constexpr int SMEM_NT = (4 * ASZ) * 2;            // 49152 B

// ---------------- kernel 1: dual QKV GEMM (single-buffer, pre-split) ----------------
__global__ void __launch_bounds__(256)
k_qkv() {
    extern __shared__ __align__(16) __nv_bfloat16 sm[];
    __nv_bfloat16 *Ah = sm, *Al = sm + ASZ, *Bh = sm + 2 * ASZ, *Bl = sm + 2 * ASZ + BSZ;
    int z = blockIdx.z;
    int i0 = blockIdx.y * 128, n0 = blockIdx.x * 128;
    int warp = threadIdx.x >> 5, wm = warp >> 2, wn = warp & 3;
    CFrag acc[4][2];
#pragma unroll
    for (int mi = 0; mi < 4; mi++)
#pragma unroll
        for (int ni = 0; ni < 2; ni++) wmma::fill_fragment(acc[mi][ni], 0.0f);

    const __nv_bfloat16* Agh = g_Xh + (size_t)i0 * HIDN;
    const __nv_bfloat16* Agl = g_Xl + (size_t)i0 * HIDN;
    const __nv_bfloat16* Bgh = g_Wh[z] + n0;
    const __nv_bfloat16* Bgl = g_Wl[z] + n0;

    uint4 rah[2], ral[2], rbh[2], rbl[2];
    ldA16(rah, Agh, HIDN); ldA16(ral, Agl, HIDN);
    ldB16(rbh, Bgh, QKVO); ldB16(rbl, Bgl, QKVO);
    const int kts = HIDN / BK;  // 64
    for (int kt = 0; kt < kts; ++kt) {
        stA16(rah, Ah); stA16(ral, Al); stB16(rbh, Bh); stB16(rbl, Bl);
        __syncthreads();
        if (kt + 1 < kts) {
            ldA16(rah, Agh + (kt + 1) * BK, HIDN);
            ldA16(ral, Agl + (kt + 1) * BK, HIDN);
            ldB16(rbh, Bgh + (size_t)(kt + 1) * BK * QKVO, QKVO);
            ldB16(rbl, Bgl + (size_t)(kt + 1) * BK * QKVO, QKVO);
        }
        mma_bf16<false>(Ah, Al, Bh, Bl, acc, wm, wn);
        __syncthreads();
    }
    epi_direct(acc, g_qkv[z] + (size_t)i0 * QKVO + n0, QKVO, wm, wn);
}

// ---------------- kernel 2a: RoPE trig tables ----------------
__global__ void k_trig(const int* __restrict__ pos) {
    int idx = blockIdx.x * 256 + threadIdx.x;
    int s = idx >> 7, d = idx & 127;
    double invf = exp(-(double)d * (13.815510557964274 / 128.0));
    double th = (double)pos[s] * invf;
    double c, sn;
    sincos(th, &c, &sn);
    g_cos[idx] = (float)c;
    g_sin[idx] = (float)sn;
}

// ---------------- kernel 2b: bias + rotation by -theta; emit split bf16 ----------------
__global__ void __launch_bounds__(256)
k_biasrope(const float* __restrict__ br, const float* __restrict__ bi) {
    int idx = blockIdx.x * 256 + threadIdx.x;
    int s = idx / QKVO;
    int c = idx - s * QKVO;
    size_t o = (size_t)s * QKVO + c;
    float xr = g_qkv[0][o] + br[c];
    float xi = g_qkv[1][o] + bi[c];
    if (c < VOFF) {
        int ti = (s << 7) | (c & 127);
        float cf = g_cos[ti], sf = g_sin[ti];
        float nr = xr * cf + xi * sf;
        float ni = -xr * sf + xi * cf;
        xr = nr; xi = ni;
    }
    __nv_bfloat16 h, l;
    split1(xr, h, l); g_qh[0][o] = h; g_ql[0][o] = l;
    split1(xi, h, l); g_qh[1][o] = h; g_ql[1][o] = l;
}

// ---------------- kernel 3: scores GEMM (NT, K=256, single-buffer) ----------------
__global__ void __launch_bounds__(256)
k_scores() {
    int h = blockIdx.z, i0 = blockIdx.y * 128, j0 = blockIdx.x * 128;
    if (j0 > i0) return;
    extern __shared__ __align__(16) __nv_bfloat16 sm[];
    __nv_bfloat16 *Ah = sm, *Al = sm + ASZ, *Bh = sm + 2 * ASZ, *Bl = sm + 3 * ASZ;
    int warp = threadIdx.x >> 5, wm = warp >> 2, wn = warp & 3;
    CFrag acc[4][2];
#pragma unroll
    for (int mi = 0; mi < 4; mi++)
#pragma unroll
        for (int ni = 0; ni < 2; ni++) wmma::fill_fragment(acc[mi][ni], 0.0f);

    uint4 rah[2], ral[2], rbh[2], rbl[2];
    ldA16(rah, g_qh[0] + (size_t)i0 * QKVO + h * DHEAD, QKVO);
    ldA16(ral, g_ql[0] + (size_t)i0 * QKVO + h * DHEAD, QKVO);
    ldA16(rbh, g_qh[0] + (size_t)j0 * QKVO + KOFF + h * DHEAD, QKVO);
    ldA16(rbl, g_ql[0] + (size_t)j0 * QKVO + KOFF + h * DHEAD, QKVO);
    for (int kt = 0; kt < 8; ++kt) {
        stA16(rah, Ah); stA16(ral, Al); stA16(rbh, Bh); stA16(rbl, Bl);
        __syncthreads();
        if (kt + 1 < 8) {
            int nk = kt + 1, pl = nk >> 2, kc = (nk & 3) * BK;
            ldA16(rah, g_qh[pl] + (size_t)i0 * QKVO + h * DHEAD + kc, QKVO);
            ldA16(ral, g_ql[pl] + (size_t)i0 * QKVO + h * DHEAD + kc, QKVO);
            ldA16(rbh, g_qh[pl] + (size_t)j0 * QKVO + KOFF + h * DHEAD + kc, QKVO);
            ldA16(rbl, g_ql[pl] + (size_t)j0 * QKVO + KOFF + h * DHEAD + kc, QKVO);
        }
        mma_bf16<true>(Ah, Al, Bh, Bl, acc, wm, wn);
        __syncthreads();
    }
    epi_direct(acc, g_scores + ((size_t)h * SEQ + i0) * SEQ + j0, SEQ, wm, wn);
}

// ---------------- kernel 4: softmax; emit split bf16 P; causal-aware IO ----------------
__device__ __forceinline__ void st4_split(__nv_bfloat16* H, __nv_bfloat16* L, int off,
                                          float a0, float a1, float a2, float a3) {
    __nv_bfloat16 h0, h1, h2, h3, l0, l1, l2, l3;
    split1(a0, h0, l0); split1(a1, h1, l1); split1(a2, h2, l2); split1(a3, h3, l3);
    *reinterpret_cast<__nv_bfloat162*>(H + off)     = __halves2bfloat162(h0, h1);
    *reinterpret_cast<__nv_bfloat162*>(H + off + 2) = __halves2bfloat162(h2, h3);
    *reinterpret_cast<__nv_bfloat162*>(L + off)     = __halves2bfloat162(l0, l1);
    *reinterpret_cast<__nv_bfloat162*>(L + off + 2) = __halves2bfloat162(l2, l3);
}

__global__ void __launch_bounds__(256)
k_softmax() {
    int bx = blockIdx.x;
    int r = bx & (SEQ - 1);
    const float* p = g_scores + (size_t)bx * SEQ;
    __nv_bfloat16* Ph = g_Ph + (size_t)bx * SEQ;
    __nv_bfloat16* Pl = g_Pl + (size_t)bx * SEQ;
    int tid = threadIdx.x;
    int c0 = tid * 4, c1 = 1024 + tid * 4;
    const float4* pv = reinterpret_cast<const float4*>(p);
    float4 v0 = (c0 <= r) ? pv[tid]       : make_float4(0.f, 0.f, 0.f, 0.f);
    float4 v1 = (c1 <= r) ? pv[tid + 256] : make_float4(0.f, 0.f, 0.f, 0.f);
    const float scale = 0.08838834764831845f;
    float a[8] = {v0.x, v0.y, v0.z, v0.w, v1.x, v1.y, v1.z, v1.w};
    int cols[8] = {c0, c0 + 1, c0 + 2, c0 + 3, c1, c1 + 1, c1 + 2, c1 + 3};

    float m = -3.4e38f;
#pragma unroll
    for (int j = 0; j < 8; j++)
        if (cols[j] <= r) { a[j] *= scale; m = fmaxf(m, a[j]); }

    __shared__ float red[8];
#pragma unroll
    for (int o = 16; o; o >>= 1) m = fmaxf(m, __shfl_xor_sync(0xffffffffu, m, o));
    if ((tid & 31) == 0) red[tid >> 5] = m;
    __syncthreads();
    float mb = fmaxf(fmaxf(fmaxf(red[0], red[1]), fmaxf(red[2], red[3])),
                     fmaxf(fmaxf(red[4], red[5]), fmaxf(red[6], red[7])));

    float s = 0.f;
#pragma unroll
    for (int j = 0; j < 8; j++) {
        a[j] = (cols[j] <= r) ? expf(a[j] - mb) : 0.f;
        s += a[j];
    }
#pragma unroll
    for (int o = 16; o; o >>= 1) s += __shfl_xor_sync(0xffffffffu, s, o);
    __syncthreads();
    if ((tid & 31) == 0) red[tid >> 5] = s;
    __syncthreads();
    float inv = 1.0f / (red[0] + red[1] + red[2] + red[3] + red[4] + red[5] + red[6] + red[7]);

    int bend = r | 127;
    if (c0 <= bend) st4_split(Ph, Pl, c0, a[0] * inv, a[1] * inv, a[2] * inv, a[3] * inv);
    if (c1 <= bend) st4_split(Ph, Pl, c1, a[4] * inv, a[5] * inv, a[6] * inv, a[7] * inv);
}

// ---------------- kernel 5: attn @ V (single-buffer) ----------------
__global__ void __launch_bounds__(256)
k_av() {
    int bz = blockIdx.z;
    int h = bz >> 1, z = bz & 1;
    int i0 = blockIdx.y * 128;
    extern __shared__ __align__(16) __nv_bfloat16 sm[];
    __nv_bfloat16 *Ah = sm, *Al = sm + ASZ, *Bh = sm + 2 * ASZ, *Bl = sm + 2 * ASZ + BSZ;
    int warp = threadIdx.x >> 5, wm = warp >> 2, wn = warp & 3;
    CFrag acc[4][2];
#pragma unroll
    for (int mi = 0; mi < 4; mi++)
#pragma unroll
        for (int ni = 0; ni < 2; ni++) wmma::fill_fragment(acc[mi][ni], 0.0f);

    const __nv_bfloat16* Agh = g_Ph + (size_t)h * SEQ * SEQ + (size_t)i0 * SEQ;
    const __nv_bfloat16* Agl = g_Pl + (size_t)h * SEQ * SEQ + (size_t)i0 * SEQ;
    const __nv_bfloat16* Bgh = g_qh[z] + VOFF + h * DHEAD;
    const __nv_bfloat16* Bgl = g_ql[z] + VOFF + h * DHEAD;

    uint4 rah[2], ral[2], rbh[2], rbl[2];
    ldA16(rah, Agh, SEQ); ldA16(ral, Agl, SEQ);
    ldB16(rbh, Bgh, QKVO); ldB16(rbl, Bgl, QKVO);
    int ktiles = (i0 + 128) / BK;
    for (int kt = 0; kt < ktiles; ++kt) {
        stA16(rah, Ah); stA16(ral, Al); stB16(rbh, Bh); stB16(rbl, Bl);
        __syncthreads();
        if (kt + 1 < ktiles) {
            ldA16(rah, Agh + (kt + 1) * BK, SEQ);
            ldA16(ral, Agl + (kt + 1) * BK, SEQ);
            ldB16(rbh, Bgh + (size_t)(kt + 1) * BK * QKVO, QKVO);
            ldB16(rbl, Bgl + (size_t)(kt + 1) * BK * QKVO, QKVO);
        }
        mma_bf16<false>(Ah, Al, Bh, Bl, acc, wm, wn);
        __syncthreads();
    }
    epi_direct(acc, g_attn[z] + (size_t)i0 * HIDN + h * DHEAD, HIDN, wm, wn);
}

// ---------------- kernel 6: output projections (single-buffer) ----------------
__global__ void __launch_bounds__(256)
k_out(float* __restrict__ out) {
    int z = blockIdx.z;
    int i0 = blockIdx.y * 128, n0 = blockIdx.x * 128;
    extern __shared__ __align__(16) __nv_bfloat16 sm[];
    __nv_bfloat16 *Ah = sm, *Al = sm + ASZ, *Bh = sm + 2 * ASZ, *Bl = sm + 2 * ASZ + BSZ;
    int warp = threadIdx.x >> 5, wm = warp >> 2, wn = warp & 3;
    CFrag acc[4][2];
#pragma unroll
    for (int mi = 0; mi < 4; mi++)
#pragma unroll
        for (int ni = 0; ni < 2; ni++) wmma::fill_fragment(acc[mi][ni], 0.0f);

    const __nv_bfloat16* Agh = g_ah[z] + (size_t)i0 * HIDN;
    const __nv_bfloat16* Agl = g_al[z] + (size_t)i0 * HIDN;
    const __nv_bfloat16* Bgh = g_Woh[z] + n0;
    const __nv_bfloat16* Bgl = g_Wol[z] + n0;

    uint4 rah[2], ral[2], rbh[2], rbl[2];
    ldA16(rah, Agh, HIDN); ldA16(ral, Agl, HIDN);
    ldB16(rbh, Bgh, HIDN); ldB16(rbl, Bgl, HIDN);
    const int kts = HIDN / BK;
    for (int kt = 0; kt < kts; ++kt) {
        stA16(rah, Ah); stA16(ral, Al); stB16(rbh, Bh); stB16(rbl, Bl);
        __syncthreads();
        if (kt + 1 < kts) {
            ldA16(rah, Agh + (kt + 1) * BK, HIDN);
            ldA16(ral, Agl + (kt + 1) * BK, HIDN);
            ldB16(rbh, Bgh + (size_t)(kt + 1) * BK * HIDN, HIDN);
            ldB16(rbl, Bgl + (size_t)(kt + 1) * BK * HIDN, HIDN);
        }
        mma_bf16<false>(Ah, Al, Bh, Bl, acc, wm, wn);
        __syncthreads();
    }
    epi_direct(acc, out + (size_t)z * SEQ * HIDN + (size_t)i0 * HIDN + n0, HIDN, wm, wn);
}

// ---------------- launch ----------------
extern "C" void kernel_launch(void* const* d_in, const int* in_sizes, int n_in,
                              void* d_out, int out_size) {
    const float* hidden = (const float*)d_in[0];
    const int*   pos    = (const int*)d_in[1];
    const float* Wqkv_r = (const float*)d_in[2];
    const float* bqkv_r = (const float*)d_in[3];
    const float* Wqkv_i = (const float*)d_in[4];
    const float* bqkv_i = (const float*)d_in[5];
    const float* Wo_r   = (const float*)d_in[6];
    const float* Wo_i   = (const float*)d_in[7];
    float* out = (float*)d_out;

    cudaFuncSetAttribute(k_qkv,    cudaFuncAttributeMaxDynamicSharedMemorySize, SMEM_NN);
    cudaFuncSetAttribute(k_scores, cudaFuncAttributeMaxDynamicSharedMemorySize, SMEM_NT);
    cudaFuncSetAttribute(k_av,     cudaFuncAttributeMaxDynamicSharedMemorySize, SMEM_NN);
    cudaFuncSetAttribute(k_out,    cudaFuncAttributeMaxDynamicSharedMemorySize, SMEM_NN);

    dim3 blk(256);
    k_trig<<<(SEQ * DHEAD) / 256, blk>>>(pos);
    k_split<<<(SEQ * HIDN) / 1024, blk>>>(hidden, 0, SEQ * HIDN);
    k_split<<<(HIDN * QKVO) / 1024, blk>>>(Wqkv_r, 1, HIDN * QKVO);
    k_split<<<(HIDN * QKVO) / 1024, blk>>>(Wqkv_i, 2, HIDN * QKVO);
    k_split<<<(HIDN * HIDN) / 1024, blk>>>(Wo_r, 3, HIDN * HIDN);
    k_split<<<(HIDN * HIDN) / 1024, blk>>>(Wo_i, 4, HIDN * HIDN);
    k_qkv<<<dim3(QKVO / 128, SEQ / 128, 2), blk, SMEM_NN>>>();
    k_biasrope<<<(SEQ * QKVO) / 256, blk>>>(bqkv_r, bqkv_i);
    k_scores<<<dim3(SEQ / 128, SEQ / 128, NHEAD), blk, SMEM_NT>>>();
    k_softmax<<<NHEAD * SEQ, blk>>>();
    k_av<<<dim3(1, SEQ / 128, NHEAD * 2), blk, SMEM_NN>>>();
    k_split<<<(2 * SEQ * HIDN) / 1024, blk>>>(nullptr, 5, 2 * SEQ * HIDN);
    int zcount = (out_size >= 2 * SEQ * HIDN) ? 2 : 1;
    k_out<<<dim3(HIDN / 128, SEQ / 128, zcount), blk, SMEM_NN>>>(out);
}

// round 13
// speedup vs baseline: 1.2928x; 1.1415x over previous
#include <cuda_runtime.h>
#include <cuda_bf16.h>
#include <mma.h>
#include <math.h>
#include <stdint.h>

using namespace nvcuda;

constexpr int SEQ   = 2048;
constexpr int HIDN  = 2048;
constexpr int NHEAD = 16;
constexpr int DHEAD = 128;
constexpr int QKVO  = 6144;
constexpr int KOFF  = 2048;
constexpr int VOFF  = 4096;

constexpr int BK   = 32;
constexpr int AKP  = 48;   // 96 B row stride
constexpr int BNPb = 144;  // 288 B row stride

// fp32 intermediates
__device__ float g_qkv[2][(size_t)SEQ * QKVO];
__device__ float g_scores[(size_t)NHEAD * SEQ * SEQ];
__device__ float g_attn[2][(size_t)SEQ * HIDN];
__device__ float g_cos[SEQ * DHEAD];
__device__ float g_sin[SEQ * DHEAD];

// pre-split bf16 hi/lo operand planes
__device__ __nv_bfloat16 g_Xh[(size_t)SEQ * HIDN],      g_Xl[(size_t)SEQ * HIDN];
__device__ __nv_bfloat16 g_Wh[2][(size_t)HIDN * QKVO],  g_Wl[2][(size_t)HIDN * QKVO];
__device__ __nv_bfloat16 g_Woh[2][(size_t)HIDN * HIDN], g_Wol[2][(size_t)HIDN * HIDN];
__device__ __nv_bfloat16 g_qh[2][(size_t)SEQ * QKVO],   g_ql[2][(size_t)SEQ * QKVO];
__device__ __nv_bfloat16 g_Ph[(size_t)NHEAD * SEQ * SEQ], g_Pl[(size_t)NHEAD * SEQ * SEQ];
__device__ __nv_bfloat16 g_ah[2][(size_t)SEQ * HIDN],   g_al[2][(size_t)SEQ * HIDN];

using AFrag  = wmma::fragment<wmma::matrix_a, 16, 16, 16, __nv_bfloat16, wmma::row_major>;
using BFragR = wmma::fragment<wmma::matrix_b, 16, 16, 16, __nv_bfloat16, wmma::row_major>;
using BFragC = wmma::fragment<wmma::matrix_b, 16, 16, 16, __nv_bfloat16, wmma::col_major>;
using CFrag  = wmma::fragment<wmma::accumulator, 16, 16, 16, float>;

__device__ __forceinline__ void split1(float x, __nv_bfloat16& h, __nv_bfloat16& l) {
    h = __float2bfloat16_rn(x);
    l = __float2bfloat16_rn(x - __bfloat162float(h));
}

__device__ __forceinline__ uint32_t smem_to_u32(const void* p) {
    uint32_t a;
    asm("{ .reg .u64 t; cvta.to.shared.u64 t, %1; cvt.u32.u64 %0, t; }" : "=r"(a) : "l"(p));
    return a;
}

// ---------------- cp.async: gmem -> smem, no staging registers ----------------
#define CP_ASYNC16(saddr, gptr) \
    asm volatile("cp.async.cg.shared.global [%0], [%1], 16;" :: "r"(saddr), "l"(gptr) : "memory")
#define CP_COMMIT() asm volatile("cp.async.commit_group;" ::: "memory")
#define CP_WAIT1()  asm volatile("cp.async.wait_group 1;" ::: "memory")
#define CP_WAIT0()  asm volatile("cp.async.wait_group 0;" ::: "memory")

// A tile: 128 rows x 32 cols bf16, smem stride 96 B
__device__ __forceinline__ void cpA(uint32_t s, const __nv_bfloat16* g, int ld) {
    int t = threadIdx.x;
#pragma unroll
    for (int i = 0; i < 2; i++) {
        int idx = t + i * 256;
        int row = idx >> 2, c = idx & 3;
        CP_ASYNC16(s + row * 96 + c * 16, g + (size_t)row * ld + c * 8);
    }
}
// B tile: 32 rows x 128 cols bf16, smem stride 288 B
__device__ __forceinline__ void cpB(uint32_t s, const __nv_bfloat16* g, int ld) {
    int t = threadIdx.x;
#pragma unroll
    for (int i = 0; i < 2; i++) {
        int idx = t + i * 256;
        int row = idx >> 4, c = idx & 15;
        CP_ASYNC16(s + row * 288 + c * 16, g + (size_t)row * ld + c * 8);
    }
}

// ---------------- bf16x3 mma core (proven layouts) ----------------
template <bool BT>
__device__ __forceinline__ void mma_bf16(const __nv_bfloat16* Ah, const __nv_bfloat16* Al,
                                         const __nv_bfloat16* Bh, const __nv_bfloat16* Bl,
                                         CFrag acc[4][2], int wm, int wn) {
#pragma unroll
    for (int kk = 0; kk < BK; kk += 16) {
        AFrag ah[4], al[4];
#pragma unroll
        for (int mi = 0; mi < 4; mi++) {
            wmma::load_matrix_sync(ah[mi], Ah + (wm * 64 + mi * 16) * AKP + kk, AKP);
            wmma::load_matrix_sync(al[mi], Al + (wm * 64 + mi * 16) * AKP + kk, AKP);
        }
#pragma unroll
        for (int ni = 0; ni < 2; ni++) {
            if constexpr (BT) {
                BFragC bh, bl;
                wmma::load_matrix_sync(bh, Bh + (wn * 32 + ni * 16) * AKP + kk, AKP);
                wmma::load_matrix_sync(bl, Bl + (wn * 32 + ni * 16) * AKP + kk, AKP);
#pragma unroll
                for (int mi = 0; mi < 4; mi++) {
                    wmma::mma_sync(acc[mi][ni], ah[mi], bh, acc[mi][ni]);
                    wmma::mma_sync(acc[mi][ni], al[mi], bh, acc[mi][ni]);
                    wmma::mma_sync(acc[mi][ni], ah[mi], bl, acc[mi][ni]);
                }
            } else {
                BFragR bh, bl;
                wmma::load_matrix_sync(bh, Bh + kk * BNPb + wn * 32 + ni * 16, BNPb);
                wmma::load_matrix_sync(bl, Bl + kk * BNPb + wn * 32 + ni * 16, BNPb);
#pragma unroll
                for (int mi = 0; mi < 4; mi++) {
                    wmma::mma_sync(acc[mi][ni], ah[mi], bh, acc[mi][ni]);
                    wmma::mma_sync(acc[mi][ni], al[mi], bh, acc[mi][ni]);
                    wmma::mma_sync(acc[mi][ni], ah[mi], bl, acc[mi][ni]);
                }
            }
        }
    }
}

__device__ __forceinline__ void epi_direct(CFrag acc[4][2], float* Cb, int ldc, int wm, int wn) {
#pragma unroll
    for (int mi = 0; mi < 4; mi++)
#pragma unroll
        for (int ni = 0; ni < 2; ni++)
            wmma::store_matrix_sync(Cb + (size_t)(wm * 64 + mi * 16) * ldc + wn * 32 + ni * 16,
                                    acc[mi][ni], ldc, wmma::mem_row_major);
}

// ---------------- elementwise fp32 -> (hi, lo) split ----------------
__global__ void __launch_bounds__(256)
k_split(const float* __restrict__ src, int which, int n) {
    __nv_bfloat16 *H, *L;
    switch (which) {
        case 0: H = g_Xh;     L = g_Xl;     break;
        case 1: H = g_Wh[0];  L = g_Wl[0];  break;
        case 2: H = g_Wh[1];  L = g_Wl[1];  break;
        case 3: H = g_Woh[0]; L = g_Wol[0]; break;
        case 4: H = g_Woh[1]; L = g_Wol[1]; break;
        default: H = g_ah[0]; L = g_al[0]; src = g_attn[0]; break;
    }
    int i = (blockIdx.x * 256 + threadIdx.x) * 4;
    if (i >= n) return;
    float4 v = *reinterpret_cast<const float4*>(src + i);
    __nv_bfloat16 h0, h1, h2, h3, l0, l1, l2, l3;
    split1(v.x, h0, l0); split1(v.y, h1, l1); split1(v.z, h2, l2); split1(v.w, h3, l3);
    *reinterpret_cast<__nv_bfloat162*>(H + i)     = __halves2bfloat162(h0, h1);
    *reinterpret_cast<__nv_bfloat162*>(H + i + 2) = __halves2bfloat162(h2, h3);
    *reinterpret_cast<__nv_bfloat162*>(L + i)     = __halves2bfloat162(l0, l1);
    *reinterpret_cast<__nv_bfloat162*>(L + i + 2) = __halves2bfloat162(l2, l3);
}

constexpr int ASZ = 128 * AKP;   // 6144 elems = 12288 B
constexpr int BSZ = 32 * BNPb;   // 4608 elems = 9216 B
constexpr int BUF_NN = 2 * 12288 + 2 * 9216;  // 43008 B per stage
constexpr int BUF_NT = 4 * 12288;             // 49152 B per stage
constexpr int SMEM_NN = 2 * BUF_NN;           // 86016
constexpr int SMEM_NT = 2 * BUF_NT;           // 98304

// ---------------- kernel 1: dual QKV GEMM (cp.async double-buffered) ----------------
__global__ void __launch_bounds__(256)
k_qkv() {
    extern __shared__ __align__(128) char smc[];
    uint32_t sb = smem_to_u32(smc);
    int z = blockIdx.z;
    int i0 = blockIdx.y * 128, n0 = blockIdx.x * 128;
    int warp = threadIdx.x >> 5, wm = warp >> 2, wn = warp & 3;
    CFrag acc[4][2];
#pragma unroll
    for (int mi = 0; mi < 4; mi++)
#pragma unroll
        for (int ni = 0; ni < 2; ni++) wmma::fill_fragment(acc[mi][ni], 0.0f);

    const __nv_bfloat16* Agh = g_Xh + (size_t)i0 * HIDN;
    const __nv_bfloat16* Agl = g_Xl + (size_t)i0 * HIDN;
    const __nv_bfloat16* Bgh = g_Wh[z] + n0;
    const __nv_bfloat16* Bgl = g_Wl[z] + n0;

    auto issue = [&](int p, int b) {
        uint32_t s = sb + b * BUF_NN;
        cpA(s,          Agh + p * BK, HIDN);
        cpA(s + 12288,  Agl + p * BK, HIDN);
        cpB(s + 24576,  Bgh + (size_t)p * BK * QKVO, QKVO);
        cpB(s + 33792,  Bgl + (size_t)p * BK * QKVO, QKVO);
        CP_COMMIT();
    };
    const int kts = HIDN / BK;  // 64
    issue(0, 0);
    issue(1, 1);
    for (int kt = 0; kt < kts; ++kt) {
        if (kt + 1 < kts) CP_WAIT1(); else CP_WAIT0();
        __syncthreads();
        const __nv_bfloat16* s = reinterpret_cast<const __nv_bfloat16*>(smc + (kt & 1) * BUF_NN);
        mma_bf16<false>(s, s + ASZ, s + 2 * ASZ, s + 2 * ASZ + BSZ, acc, wm, wn);
        __syncthreads();
        if (kt + 2 < kts) issue(kt + 2, kt & 1);
    }
    epi_direct(acc, g_qkv[z] + (size_t)i0 * QKVO + n0, QKVO, wm, wn);
}

// ---------------- kernel 2a: RoPE trig tables ----------------
__global__ void k_trig(const int* __restrict__ pos) {
    int idx = blockIdx.x * 256 + threadIdx.x;
    int s = idx >> 7, d = idx & 127;
    double invf = exp(-(double)d * (13.815510557964274 / 128.0));
    double th = (double)pos[s] * invf;
    double c, sn;
    sincos(th, &c, &sn);
    g_cos[idx] = (float)c;
    g_sin[idx] = (float)sn;
}

// ---------------- kernel 2b: bias + rotation by -theta (verified); emit split ----------------
__global__ void __launch_bounds__(256)
k_biasrope(const float* __restrict__ br, const float* __restrict__ bi) {
    int idx = blockIdx.x * 256 + threadIdx.x;
    int s = idx / QKVO;
    int c = idx - s * QKVO;
    size_t o = (size_t)s * QKVO + c;
    float xr = g_qkv[0][o] + br[c];
    float xi = g_qkv[1][o] + bi[c];
    if (c < VOFF) {
        int ti = (s << 7) | (c & 127);
        float cf = g_cos[ti], sf = g_sin[ti];
        float nr = xr * cf + xi * sf;
        float ni = -xr * sf + xi * cf;
        xr = nr; xi = ni;
    }
    __nv_bfloat16 h, l;
    split1(xr, h, l); g_qh[0][o] = h; g_ql[0][o] = l;
    split1(xi, h, l); g_qh[1][o] = h; g_ql[1][o] = l;
}

// ---------------- kernel 3: scores GEMM (NT, K=256, cp.async pipelined) ----------------
__global__ void __launch_bounds__(256)
k_scores() {
    int h = blockIdx.z, i0 = blockIdx.y * 128, j0 = blockIdx.x * 128;
    if (j0 > i0) return;
    extern __shared__ __align__(128) char smc[];
    uint32_t sb = smem_to_u32(smc);
    int warp = threadIdx.x >> 5, wm = warp >> 2, wn = warp & 3;
    CFrag acc[4][2];
#pragma unroll
    for (int mi = 0; mi < 4; mi++)
#pragma unroll
        for (int ni = 0; ni < 2; ni++) wmma::fill_fragment(acc[mi][ni], 0.0f);

    auto issue = [&](int p, int b) {
        int pl = p >> 2, kc = (p & 3) * BK;
        uint32_t s = sb + b * BUF_NT;
        cpA(s,          g_qh[pl] + (size_t)i0 * QKVO + h * DHEAD + kc, QKVO);
        cpA(s + 12288,  g_ql[pl] + (size_t)i0 * QKVO + h * DHEAD + kc, QKVO);
        cpA(s + 24576,  g_qh[pl] + (size_t)j0 * QKVO + KOFF + h * DHEAD + kc, QKVO);
        cpA(s + 36864,  g_ql[pl] + (size_t)j0 * QKVO + KOFF + h * DHEAD + kc, QKVO);
        CP_COMMIT();
    };
    issue(0, 0);
    issue(1, 1);
    for (int kt = 0; kt < 8; ++kt) {
        if (kt + 1 < 8) CP_WAIT1(); else CP_WAIT0();
        __syncthreads();
        const __nv_bfloat16* s = reinterpret_cast<const __nv_bfloat16*>(smc + (kt & 1) * BUF_NT);
        mma_bf16<true>(s, s + ASZ, s + 2 * ASZ, s + 3 * ASZ, acc, wm, wn);
        __syncthreads();
        if (kt + 2 < 8) issue(kt + 2, kt & 1);
    }
    epi_direct(acc, g_scores + ((size_t)h * SEQ + i0) * SEQ + j0, SEQ, wm, wn);
}

// ---------------- kernel 4: softmax; emit split bf16 P; causal-aware IO ----------------
__device__ __forceinline__ void st4_split(__nv_bfloat16* H, __nv_bfloat16* L, int off,
                                          float a0, float a1, float a2, float a3) {
    __nv_bfloat16 h0, h1, h2, h3, l0, l1, l2, l3;
    split1(a0, h0, l0); split1(a1, h1, l1); split1(a2, h2, l2); split1(a3, h3, l3);
    *reinterpret_cast<__nv_bfloat162*>(H + off)     = __halves2bfloat162(h0, h1);
    *reinterpret_cast<__nv_bfloat162*>(H + off + 2) = __halves2bfloat162(h2, h3);
    *reinterpret_cast<__nv_bfloat162*>(L + off)     = __halves2bfloat162(l0, l1);
    *reinterpret_cast<__nv_bfloat162*>(L + off + 2) = __halves2bfloat162(l2, l3);
}

__global__ void __launch_bounds__(256)
k_softmax() {
    int bx = blockIdx.x;
    int r = bx & (SEQ - 1);
    const float* p = g_scores + (size_t)bx * SEQ;
    __nv_bfloat16* Ph = g_Ph + (size_t)bx * SEQ;
    __nv_bfloat16* Pl = g_Pl + (size_t)bx * SEQ;
    int tid = threadIdx.x;
    int c0 = tid * 4, c1 = 1024 + tid * 4;
    const float4* pv = reinterpret_cast<const float4*>(p);
    float4 v0 = (c0 <= r) ? pv[tid]       : make_float4(0.f, 0.f, 0.f, 0.f);
    float4 v1 = (c1 <= r) ? pv[tid + 256] : make_float4(0.f, 0.f, 0.f, 0.f);
    const float scale = 0.08838834764831845f;
    float a[8] = {v0.x, v0.y, v0.z, v0.w, v1.x, v1.y, v1.z, v1.w};
    int cols[8] = {c0, c0 + 1, c0 + 2, c0 + 3, c1, c1 + 1, c1 + 2, c1 + 3};

    float m = -3.4e38f;
#pragma unroll
    for (int j = 0; j < 8; j++)
        if (cols[j] <= r) { a[j] *= scale; m = fmaxf(m, a[j]); }

    __shared__ float red[8];
#pragma unroll
    for (int o = 16; o; o >>= 1) m = fmaxf(m, __shfl_xor_sync(0xffffffffu, m, o));
    if ((tid & 31) == 0) red[tid >> 5] = m;
    __syncthreads();
    float mb = fmaxf(fmaxf(fmaxf(red[0], red[1]), fmaxf(red[2], red[3])),
                     fmaxf(fmaxf(red[4], red[5]), fmaxf(red[6], red[7])));

    float s = 0.f;
#pragma unroll
    for (int j = 0; j < 8; j++) {
        a[j] = (cols[j] <= r) ? expf(a[j] - mb) : 0.f;
        s += a[j];
    }
#pragma unroll
    for (int o = 16; o; o >>= 1) s += __shfl_xor_sync(0xffffffffu, s, o);
    __syncthreads();
    if ((tid & 31) == 0) red[tid >> 5] = s;
    __syncthreads();
    float inv = 1.0f / (red[0] + red[1] + red[2] + red[3] + red[4] + red[5] + red[6] + red[7]);

    int bend = r | 127;
    if (c0 <= bend) st4_split(Ph, Pl, c0, a[0] * inv, a[1] * inv, a[2] * inv, a[3] * inv);
    if (c1 <= bend) st4_split(Ph, Pl, c1, a[4] * inv, a[5] * inv, a[6] * inv, a[7] * inv);
}

// ---------------- kernel 5: attn @ V (cp.async pipelined) ----------------
__global__ void __launch_bounds__(256)
k_av() {
    int bz = blockIdx.z;
    int h = bz >> 1, z = bz & 1;
    int i0 = blockIdx.y * 128;
    extern __shared__ __align__(128) char smc[];
    uint32_t sb = smem_to_u32(smc);
    int warp = threadIdx.x >> 5, wm = warp >> 2, wn = warp & 3;
    CFrag acc[4][2];
#pragma unroll
    for (int mi = 0; mi < 4; mi++)
#pragma unroll
        for (int ni = 0; ni < 2; ni++) wmma::fill_fragment(acc[mi][ni], 0.0f);

    const __nv_bfloat16* Agh = g_Ph + (size_t)h * SEQ * SEQ + (size_t)i0 * SEQ;
    const __nv_bfloat16* Agl = g_Pl + (size_t)h * SEQ * SEQ + (size_t)i0 * SEQ;
    const __nv_bfloat16* Bgh = g_qh[z] + VOFF + h * DHEAD;
    const __nv_bfloat16* Bgl = g_ql[z] + VOFF + h * DHEAD;

    auto issue = [&](int p, int b) {
        uint32_t s = sb + b * BUF_NN;
        cpA(s,          Agh + p * BK, SEQ);
        cpA(s + 12288,  Agl + p * BK, SEQ);
        cpB(s + 24576,  Bgh + (size_t)p * BK * QKVO, QKVO);
        cpB(s + 33792,  Bgl + (size_t)p * BK * QKVO, QKVO);
        CP_COMMIT();
    };
    int ktiles = (i0 + 128) / BK;  // >= 4
    issue(0, 0);
    issue(1, 1);
    for (int kt = 0; kt < ktiles; ++kt) {
        if (kt + 1 < ktiles) CP_WAIT1(); else CP_WAIT0();
        __syncthreads();
        const __nv_bfloat16* s = reinterpret_cast<const __nv_bfloat16*>(smc + (kt & 1) * BUF_NN);
        mma_bf16<false>(s, s + ASZ, s + 2 * ASZ, s + 2 * ASZ + BSZ, acc, wm, wn);
        __syncthreads();
        if (kt + 2 < ktiles) issue(kt + 2, kt & 1);
    }
    epi_direct(acc, g_attn[z] + (size_t)i0 * HIDN + h * DHEAD, HIDN, wm, wn);
}

// ---------------- kernel 6: output projections (cp.async pipelined) ----------------
__global__ void __launch_bounds__(256)
k_out(float* __restrict__ out) {
    int z = blockIdx.z;
    int i0 = blockIdx.y * 128, n0 = blockIdx.x * 128;
    extern __shared__ __align__(128) char smc[];
    uint32_t sb = smem_to_u32(smc);
    int warp = threadIdx.x >> 5, wm = warp >> 2, wn = warp & 3;
    CFrag acc[4][2];
#pragma unroll
    for (int mi = 0; mi < 4; mi++)
#pragma unroll
        for (int ni = 0; ni < 2; ni++) wmma::fill_fragment(acc[mi][ni], 0.0f);

    const __nv_bfloat16* Agh = g_ah[z] + (size_t)i0 * HIDN;
    const __nv_bfloat16* Agl = g_al[z] + (size_t)i0 * HIDN;
    const __nv_bfloat16* Bgh = g_Woh[z] + n0;
    const __nv_bfloat16* Bgl = g_Wol[z] + n0;

    auto issue = [&](int p, int b) {
        uint32_t s = sb + b * BUF_NN;
        cpA(s,          Agh + p * BK, HIDN);
        cpA(s + 12288,  Agl + p * BK, HIDN);
        cpB(s + 24576,  Bgh + (size_t)p * BK * HIDN, HIDN);
        cpB(s + 33792,  Bgl + (size_t)p * BK * HIDN, HIDN);
        CP_COMMIT();
    };
    const int kts = HIDN / BK;  // 64
    issue(0, 0);
    issue(1, 1);
    for (int kt = 0; kt < kts; ++kt) {
        if (kt + 1 < kts) CP_WAIT1(); else CP_WAIT0();
        __syncthreads();
        const __nv_bfloat16* s = reinterpret_cast<const __nv_bfloat16*>(smc + (kt & 1) * BUF_NN);
        mma_bf16<false>(s, s + ASZ, s + 2 * ASZ, s + 2 * ASZ + BSZ, acc, wm, wn);
        __syncthreads();
        if (kt + 2 < kts) issue(kt + 2, kt & 1);
    }
    epi_direct(acc, out + (size_t)z * SEQ * HIDN + (size_t)i0 * HIDN + n0, HIDN, wm, wn);
}

// ---------------- launch ----------------
extern "C" void kernel_launch(void* const* d_in, const int* in_sizes, int n_in,
                              void* d_out, int out_size) {
    const float* hidden = (const float*)d_in[0];
    const int*   pos    = (const int*)d_in[1];
    const float* Wqkv_r = (const float*)d_in[2];
    const float* bqkv_r = (const float*)d_in[3];
    const float* Wqkv_i = (const float*)d_in[4];
    const float* bqkv_i = (const float*)d_in[5];
    const float* Wo_r   = (const float*)d_in[6];
    const float* Wo_i   = (const float*)d_in[7];
    float* out = (float*)d_out;

    cudaFuncSetAttribute(k_qkv,    cudaFuncAttributeMaxDynamicSharedMemorySize, SMEM_NN);
    cudaFuncSetAttribute(k_scores, cudaFuncAttributeMaxDynamicSharedMemorySize, SMEM_NT);
    cudaFuncSetAttribute(k_av,     cudaFuncAttributeMaxDynamicSharedMemorySize, SMEM_NN);
    cudaFuncSetAttribute(k_out,    cudaFuncAttributeMaxDynamicSharedMemorySize, SMEM_NN);

    dim3 blk(256);
    k_trig<<<(SEQ * DHEAD) / 256, blk>>>(pos);
    k_split<<<(SEQ * HIDN) / 1024, blk>>>(hidden, 0, SEQ * HIDN);
    k_split<<<(HIDN * QKVO) / 1024, blk>>>(Wqkv_r, 1, HIDN * QKVO);
    k_split<<<(HIDN * QKVO) / 1024, blk>>>(Wqkv_i, 2, HIDN * QKVO);
    k_split<<<(HIDN * HIDN) / 1024, blk>>>(Wo_r, 3, HIDN * HIDN);
    k_split<<<(HIDN * HIDN) / 1024, blk>>>(Wo_i, 4, HIDN * HIDN);
    k_qkv<<<dim3(QKVO / 128, SEQ / 128, 2), blk, SMEM_NN>>>();
    k_biasrope<<<(SEQ * QKVO) / 256, blk>>>(bqkv_r, bqkv_i);
    k_scores<<<dim3(SEQ / 128, SEQ / 128, NHEAD), blk, SMEM_NT>>>();
    k_softmax<<<NHEAD * SEQ, blk>>>();
    k_av<<<dim3(1, SEQ / 128, NHEAD * 2), blk, SMEM_NN>>>();
    k_split<<<(2 * SEQ * HIDN) / 1024, blk>>>(nullptr, 5, 2 * SEQ * HIDN);
    int zcount = (out_size >= 2 * SEQ * HIDN) ? 2 : 1;
    k_out<<<dim3(HIDN / 128, SEQ / 128, zcount), blk, SMEM_NN>>>(out);
}

// round 14
// speedup vs baseline: 1.3667x; 1.0571x over previous
#include <cuda_runtime.h>
#include <cuda_bf16.h>
#include <mma.h>
#include <math.h>
#include <stdint.h>

using namespace nvcuda;

constexpr int SEQ   = 2048;
constexpr int HIDN  = 2048;
constexpr int NHEAD = 16;
constexpr int DHEAD = 128;
constexpr int QKVO  = 6144;
constexpr int KOFF  = 2048;
constexpr int VOFF  = 4096;

constexpr int BK   = 32;
constexpr int AKP  = 48;    // A tile: 96 B row stride
constexpr int BNPb = 144;   // B tile 128-wide: 288 B row stride
constexpr int BNP2 = 272;   // B tile 256-wide: 544 B row stride

// fp32 intermediates
__device__ float g_qkv[2][(size_t)SEQ * QKVO];
__device__ float g_scores[(size_t)NHEAD * SEQ * SEQ];
__device__ float g_attn[2][(size_t)SEQ * HIDN];
__device__ float g_cos[SEQ * DHEAD];
__device__ float g_sin[SEQ * DHEAD];

// pre-split bf16 hi/lo operand planes
__device__ __nv_bfloat16 g_Xh[(size_t)SEQ * HIDN],      g_Xl[(size_t)SEQ * HIDN];
__device__ __nv_bfloat16 g_Wh[2][(size_t)HIDN * QKVO],  g_Wl[2][(size_t)HIDN * QKVO];
__device__ __nv_bfloat16 g_Woh[2][(size_t)HIDN * HIDN], g_Wol[2][(size_t)HIDN * HIDN];
__device__ __nv_bfloat16 g_qh[2][(size_t)SEQ * QKVO],   g_ql[2][(size_t)SEQ * QKVO];
__device__ __nv_bfloat16 g_Ph[(size_t)NHEAD * SEQ * SEQ], g_Pl[(size_t)NHEAD * SEQ * SEQ];
__device__ __nv_bfloat16 g_ah[2][(size_t)SEQ * HIDN],   g_al[2][(size_t)SEQ * HIDN];

using AFrag  = wmma::fragment<wmma::matrix_a, 16, 16, 16, __nv_bfloat16, wmma::row_major>;
using BFragR = wmma::fragment<wmma::matrix_b, 16, 16, 16, __nv_bfloat16, wmma::row_major>;
using BFragC = wmma::fragment<wmma::matrix_b, 16, 16, 16, __nv_bfloat16, wmma::col_major>;
using CFrag  = wmma::fragment<wmma::accumulator, 16, 16, 16, float>;

__device__ __forceinline__ void split1(float x, __nv_bfloat16& h, __nv_bfloat16& l) {
    h = __float2bfloat16_rn(x);
    l = __float2bfloat16_rn(x - __bfloat162float(h));
}
__device__ __forceinline__ uint32_t smem_to_u32(const void* p) {
    uint32_t a;
    asm("{ .reg .u64 t; cvta.to.shared.u64 t, %1; cvt.u32.u64 %0, t; }" : "=r"(a) : "l"(p));
    return a;
}

// ---------------- cp.async ----------------
#define CP_ASYNC16(saddr, gptr) \
    asm volatile("cp.async.cg.shared.global [%0], [%1], 16;" :: "r"(saddr), "l"(gptr) : "memory")
#define CP_COMMIT() asm volatile("cp.async.commit_group;" ::: "memory")
#define CP_WAIT1()  asm volatile("cp.async.wait_group 1;" ::: "memory")
#define CP_WAIT0()  asm volatile("cp.async.wait_group 0;" ::: "memory")

// A tile: 128x32 bf16, stride 96 B (512 xfers)
__device__ __forceinline__ void cpA(uint32_t s, const __nv_bfloat16* g, int ld) {
    int t = threadIdx.x;
#pragma unroll
    for (int i = 0; i < 2; i++) {
        int idx = t + i * 256;
        int row = idx >> 2, c = idx & 3;
        CP_ASYNC16(s + row * 96 + c * 16, g + (size_t)row * ld + c * 8);
    }
}
// B tile: 32x128 bf16, stride 288 B (512 xfers)
__device__ __forceinline__ void cpB(uint32_t s, const __nv_bfloat16* g, int ld) {
    int t = threadIdx.x;
#pragma unroll
    for (int i = 0; i < 2; i++) {
        int idx = t + i * 256;
        int row = idx >> 4, c = idx & 15;
        CP_ASYNC16(s + row * 288 + c * 16, g + (size_t)row * ld + c * 8);
    }
}
// B tile: 32x256 bf16, stride 544 B (1024 xfers)
__device__ __forceinline__ void cpB256(uint32_t s, const __nv_bfloat16* g, int ld) {
    int t = threadIdx.x;
#pragma unroll
    for (int i = 0; i < 4; i++) {
        int idx = t + i * 256;
        int row = idx >> 5, c = idx & 31;
        CP_ASYNC16(s + row * 544 + c * 16, g + (size_t)row * ld + c * 8);
    }
}

// ---------------- mma cores ----------------
// 128x128 tile, 8 warps 2x4, warp tile 64x32 (proven layouts)
template <bool BT>
__device__ __forceinline__ void mma_bf16(const __nv_bfloat16* Ah, const __nv_bfloat16* Al,
                                         const __nv_bfloat16* Bh, const __nv_bfloat16* Bl,
                                         CFrag acc[4][2], int wm, int wn) {
#pragma unroll
    for (int kk = 0; kk < BK; kk += 16) {
        AFrag ah[4], al[4];
#pragma unroll
        for (int mi = 0; mi < 4; mi++) {
            wmma::load_matrix_sync(ah[mi], Ah + (wm * 64 + mi * 16) * AKP + kk, AKP);
            wmma::load_matrix_sync(al[mi], Al + (wm * 64 + mi * 16) * AKP + kk, AKP);
        }
#pragma unroll
        for (int ni = 0; ni < 2; ni++) {
            if constexpr (BT) {
                BFragC bh, bl;
                wmma::load_matrix_sync(bh, Bh + (wn * 32 + ni * 16) * AKP + kk, AKP);
                wmma::load_matrix_sync(bl, Bl + (wn * 32 + ni * 16) * AKP + kk, AKP);
#pragma unroll
                for (int mi = 0; mi < 4; mi++) {
                    wmma::mma_sync(acc[mi][ni], ah[mi], bh, acc[mi][ni]);
                    wmma::mma_sync(acc[mi][ni], al[mi], bh, acc[mi][ni]);
                    wmma::mma_sync(acc[mi][ni], ah[mi], bl, acc[mi][ni]);
                }
            } else {
                BFragR bh, bl;
                wmma::load_matrix_sync(bh, Bh + kk * BNPb + wn * 32 + ni * 16, BNPb);
                wmma::load_matrix_sync(bl, Bl + kk * BNPb + wn * 32 + ni * 16, BNPb);
#pragma unroll
                for (int mi = 0; mi < 4; mi++) {
                    wmma::mma_sync(acc[mi][ni], ah[mi], bh, acc[mi][ni]);
                    wmma::mma_sync(acc[mi][ni], al[mi], bh, acc[mi][ni]);
                    wmma::mma_sync(acc[mi][ni], ah[mi], bl, acc[mi][ni]);
                }
            }
        }
    }
}

// 128x256 tile, 8 warps 2x4, warp tile 64x64 (A fragment reused over 4 N-strips)
__device__ __forceinline__ void mma_w(const __nv_bfloat16* Ah, const __nv_bfloat16* Al,
                                      const __nv_bfloat16* Bh, const __nv_bfloat16* Bl,
                                      CFrag acc[4][4], int wm, int wn) {
#pragma unroll
    for (int kk = 0; kk < BK; kk += 16) {
        AFrag ah[4], al[4];
#pragma unroll
        for (int mi = 0; mi < 4; mi++) {
            wmma::load_matrix_sync(ah[mi], Ah + (wm * 64 + mi * 16) * AKP + kk, AKP);
            wmma::load_matrix_sync(al[mi], Al + (wm * 64 + mi * 16) * AKP + kk, AKP);
        }
#pragma unroll
        for (int ni = 0; ni < 4; ni++) {
            BFragR bh, bl;
            wmma::load_matrix_sync(bh, Bh + kk * BNP2 + wn * 64 + ni * 16, BNP2);
            wmma::load_matrix_sync(bl, Bl + kk * BNP2 + wn * 64 + ni * 16, BNP2);
#pragma unroll
            for (int mi = 0; mi < 4; mi++) {
                wmma::mma_sync(acc[mi][ni], ah[mi], bh, acc[mi][ni]);
                wmma::mma_sync(acc[mi][ni], al[mi], bh, acc[mi][ni]);
                wmma::mma_sync(acc[mi][ni], ah[mi], bl, acc[mi][ni]);
            }
        }
    }
}

__device__ __forceinline__ void epi_direct(CFrag acc[4][2], float* Cb, int ldc, int wm, int wn) {
#pragma unroll
    for (int mi = 0; mi < 4; mi++)
#pragma unroll
        for (int ni = 0; ni < 2; ni++)
            wmma::store_matrix_sync(Cb + (size_t)(wm * 64 + mi * 16) * ldc + wn * 32 + ni * 16,
                                    acc[mi][ni], ldc, wmma::mem_row_major);
}
__device__ __forceinline__ void epi_w(CFrag acc[4][4], float* Cb, int ldc, int wm, int wn) {
#pragma unroll
    for (int mi = 0; mi < 4; mi++)
#pragma unroll
        for (int ni = 0; ni < 4; ni++)
            wmma::store_matrix_sync(Cb + (size_t)(wm * 64 + mi * 16) * ldc + wn * 64 + ni * 16,
                                    acc[mi][ni], ldc, wmma::mem_row_major);
}

// ---------------- elementwise fp32 -> (hi, lo) split ----------------
__global__ void __launch_bounds__(256)
k_split(const float* __restrict__ src, int which, int n) {
    __nv_bfloat16 *H, *L;
    switch (which) {
        case 0: H = g_Xh;     L = g_Xl;     break;
        case 1: H = g_Wh[0];  L = g_Wl[0];  break;
        case 2: H = g_Wh[1];  L = g_Wl[1];  break;
        case 3: H = g_Woh[0]; L = g_Wol[0]; break;
        case 4: H = g_Woh[1]; L = g_Wol[1]; break;
        default: H = g_ah[0]; L = g_al[0]; src = g_attn[0]; break;
    }
    int i = (blockIdx.x * 256 + threadIdx.x) * 4;
    if (i >= n) return;
    float4 v = *reinterpret_cast<const float4*>(src + i);
    __nv_bfloat16 h0, h1, h2, h3, l0, l1, l2, l3;
    split1(v.x, h0, l0); split1(v.y, h1, l1); split1(v.z, h2, l2); split1(v.w, h3, l3);
    *reinterpret_cast<__nv_bfloat162*>(H + i)     = __halves2bfloat162(h0, h1);
    *reinterpret_cast<__nv_bfloat162*>(H + i + 2) = __halves2bfloat162(h2, h3);
    *reinterpret_cast<__nv_bfloat162*>(L + i)     = __halves2bfloat162(l0, l1);
    *reinterpret_cast<__nv_bfloat162*>(L + i + 2) = __halves2bfloat162(l2, l3);
}

constexpr int ASZ = 128 * AKP;                 // 6144 elems = 12288 B
constexpr int BSZ = 32 * BNPb;                 // 4608 elems = 9216 B
constexpr int B2SZ = 32 * BNP2;                // 8704 elems = 17408 B
constexpr int BUF_NN  = 2 * 12288 + 2 * 9216;   // 43008 B
constexpr int BUF_NT  = 4 * 12288;              // 49152 B
constexpr int BUF_W   = 2 * 12288 + 2 * 17408;  // 59392 B
constexpr int SMEM_NN = 3 * BUF_NN;             // 129024
constexpr int SMEM_NT = 3 * BUF_NT;             // 147456
constexpr int SMEM_W  = 3 * BUF_W;              // 178176

// ---------------- kernel 1: dual QKV GEMM (128x256, 3-stage, 1 sync/tile) ----------------
__global__ void __launch_bounds__(256)
k_qkv() {
    extern __shared__ __align__(128) char smc[];
    uint32_t sb = smem_to_u32(smc);
    int z = blockIdx.z;
    int i0 = blockIdx.y * 128, n0 = blockIdx.x * 256;
    int warp = threadIdx.x >> 5, wm = warp >> 2, wn = warp & 3;
    CFrag acc[4][4];
#pragma unroll
    for (int mi = 0; mi < 4; mi++)
#pragma unroll
        for (int ni = 0; ni < 4; ni++) wmma::fill_fragment(acc[mi][ni], 0.0f);

    const __nv_bfloat16* Agh = g_Xh + (size_t)i0 * HIDN;
    const __nv_bfloat16* Agl = g_Xl + (size_t)i0 * HIDN;
    const __nv_bfloat16* Bgh = g_Wh[z] + n0;
    const __nv_bfloat16* Bgl = g_Wl[z] + n0;

    auto issue = [&](int p) {
        uint32_t s = sb + (p % 3) * BUF_W;
        cpA(s,            Agh + p * BK, HIDN);
        cpA(s + 12288,    Agl + p * BK, HIDN);
        cpB256(s + 24576, Bgh + (size_t)p * BK * QKVO, QKVO);
        cpB256(s + 41984, Bgl + (size_t)p * BK * QKVO, QKVO);
        CP_COMMIT();
    };
    const int kts = HIDN / BK;  // 64
    issue(0);
    issue(1);
    for (int kt = 0; kt < kts; ++kt) {
        if (kt + 1 < kts) CP_WAIT1(); else CP_WAIT0();
        __syncthreads();
        const __nv_bfloat16* s = reinterpret_cast<const __nv_bfloat16*>(smc + (kt % 3) * BUF_W);
        mma_w(s, s + ASZ, s + 2 * ASZ, s + 2 * ASZ + B2SZ, acc, wm, wn);
        if (kt + 2 < kts) issue(kt + 2);
    }
    epi_w(acc, g_qkv[z] + (size_t)i0 * QKVO + n0, QKVO, wm, wn);
}

// ---------------- kernel 2a: RoPE trig tables ----------------
__global__ void k_trig(const int* __restrict__ pos) {
    int idx = blockIdx.x * 256 + threadIdx.x;
    int s = idx >> 7, d = idx & 127;
    double invf = exp(-(double)d * (13.815510557964274 / 128.0));
    double th = (double)pos[s] * invf;
    double c, sn;
    sincos(th, &c, &sn);
    g_cos[idx] = (float)c;
    g_sin[idx] = (float)sn;
}

// ---------------- kernel 2b: bias + rotation by -theta; emit split bf16 ----------------
__global__ void __launch_bounds__(256)
k_biasrope(const float* __restrict__ br, const float* __restrict__ bi) {
    int idx = blockIdx.x * 256 + threadIdx.x;
    int s = idx / QKVO;
    int c = idx - s * QKVO;
    size_t o = (size_t)s * QKVO + c;
    float xr = g_qkv[0][o] + br[c];
    float xi = g_qkv[1][o] + bi[c];
    if (c < VOFF) {
        int ti = (s << 7) | (c & 127);
        float cf = g_cos[ti], sf = g_sin[ti];
        float nr = xr * cf + xi * sf;
        float ni = -xr * sf + xi * cf;
        xr = nr; xi = ni;
    }
    __nv_bfloat16 h, l;
    split1(xr, h, l); g_qh[0][o] = h; g_ql[0][o] = l;
    split1(xi, h, l); g_qh[1][o] = h; g_ql[1][o] = l;
}

// ---------------- kernel 3: scores GEMM (NT, 3-stage, 1 sync/tile) ----------------
__global__ void __launch_bounds__(256)
k_scores() {
    int h = blockIdx.z, i0 = blockIdx.y * 128, j0 = blockIdx.x * 128;
    if (j0 > i0) return;
    extern __shared__ __align__(128) char smc[];
    uint32_t sb = smem_to_u32(smc);
    int warp = threadIdx.x >> 5, wm = warp >> 2, wn = warp & 3;
    CFrag acc[4][2];
#pragma unroll
    for (int mi = 0; mi < 4; mi++)
#pragma unroll
        for (int ni = 0; ni < 2; ni++) wmma::fill_fragment(acc[mi][ni], 0.0f);

    auto issue = [&](int p) {
        int pl = p >> 2, kc = (p & 3) * BK;
        uint32_t s = sb + (p % 3) * BUF_NT;
        cpA(s,          g_qh[pl] + (size_t)i0 * QKVO + h * DHEAD + kc, QKVO);
        cpA(s + 12288,  g_ql[pl] + (size_t)i0 * QKVO + h * DHEAD + kc, QKVO);
        cpA(s + 24576,  g_qh[pl] + (size_t)j0 * QKVO + KOFF + h * DHEAD + kc, QKVO);
        cpA(s + 36864,  g_ql[pl] + (size_t)j0 * QKVO + KOFF + h * DHEAD + kc, QKVO);
        CP_COMMIT();
    };
    issue(0);
    issue(1);
    for (int kt = 0; kt < 8; ++kt) {
        if (kt + 1 < 8) CP_WAIT1(); else CP_WAIT0();
        __syncthreads();
        const __nv_bfloat16* s = reinterpret_cast<const __nv_bfloat16*>(smc + (kt % 3) * BUF_NT);
        mma_bf16<true>(s, s + ASZ, s + 2 * ASZ, s + 3 * ASZ, acc, wm, wn);
        if (kt + 2 < 8) issue(kt + 2);
    }
    epi_direct(acc, g_scores + ((size_t)h * SEQ + i0) * SEQ + j0, SEQ, wm, wn);
}

// ---------------- kernel 4: softmax; emit split bf16 P ----------------
__device__ __forceinline__ void st4_split(__nv_bfloat16* H, __nv_bfloat16* L, int off,
                                          float a0, float a1, float a2, float a3) {
    __nv_bfloat16 h0, h1, h2, h3, l0, l1, l2, l3;
    split1(a0, h0, l0); split1(a1, h1, l1); split1(a2, h2, l2); split1(a3, h3, l3);
    *reinterpret_cast<__nv_bfloat162*>(H + off)     = __halves2bfloat162(h0, h1);
    *reinterpret_cast<__nv_bfloat162*>(H + off + 2) = __halves2bfloat162(h2, h3);
    *reinterpret_cast<__nv_bfloat162*>(L + off)     = __halves2bfloat162(l0, l1);
    *reinterpret_cast<__nv_bfloat162*>(L + off + 2) = __halves2bfloat162(l2, l3);
}

__global__ void __launch_bounds__(256)
k_softmax() {
    int bx = blockIdx.x;
    int r = bx & (SEQ - 1);
    const float* p = g_scores + (size_t)bx * SEQ;
    __nv_bfloat16* Ph = g_Ph + (size_t)bx * SEQ;
    __nv_bfloat16* Pl = g_Pl + (size_t)bx * SEQ;
    int tid = threadIdx.x;
    int c0 = tid * 4, c1 = 1024 + tid * 4;
    const float4* pv = reinterpret_cast<const float4*>(p);
    float4 v0 = (c0 <= r) ? pv[tid]       : make_float4(0.f, 0.f, 0.f, 0.f);
    float4 v1 = (c1 <= r) ? pv[tid + 256] : make_float4(0.f, 0.f, 0.f, 0.f);
    const float scale = 0.08838834764831845f;
    float a[8] = {v0.x, v0.y, v0.z, v0.w, v1.x, v1.y, v1.z, v1.w};
    int cols[8] = {c0, c0 + 1, c0 + 2, c0 + 3, c1, c1 + 1, c1 + 2, c1 + 3};

    float m = -3.4e38f;
#pragma unroll
    for (int j = 0; j < 8; j++)
        if (cols[j] <= r) { a[j] *= scale; m = fmaxf(m, a[j]); }

    __shared__ float red[8];
#pragma unroll
    for (int o = 16; o; o >>= 1) m = fmaxf(m, __shfl_xor_sync(0xffffffffu, m, o));
    if ((tid & 31) == 0) red[tid >> 5] = m;
    __syncthreads();
    float mb = fmaxf(fmaxf(fmaxf(red[0], red[1]), fmaxf(red[2], red[3])),
                     fmaxf(fmaxf(red[4], red[5]), fmaxf(red[6], red[7])));

    float s = 0.f;
#pragma unroll
    for (int j = 0; j < 8; j++) {
        a[j] = (cols[j] <= r) ? expf(a[j] - mb) : 0.f;
        s += a[j];
    }
#pragma unroll
    for (int o = 16; o; o >>= 1) s += __shfl_xor_sync(0xffffffffu, s, o);
    __syncthreads();
    if ((tid & 31) == 0) red[tid >> 5] = s;
    __syncthreads();
    float inv = 1.0f / (red[0] + red[1] + red[2] + red[3] + red[4] + red[5] + red[6] + red[7]);

    int bend = r | 127;
    if (c0 <= bend) st4_split(Ph, Pl, c0, a[0] * inv, a[1] * inv, a[2] * inv, a[3] * inv);
    if (c1 <= bend) st4_split(Ph, Pl, c1, a[4] * inv, a[5] * inv, a[6] * inv, a[7] * inv);
}

// ---------------- kernel 5: attn @ V (3-stage, 1 sync/tile) ----------------
__global__ void __launch_bounds__(256)
k_av() {
    int bz = blockIdx.z;
    int h = bz >> 1, z = bz & 1;
    int i0 = blockIdx.y * 128;
    extern __shared__ __align__(128) char smc[];
    uint32_t sb = smem_to_u32(smc);
    int warp = threadIdx.x >> 5, wm = warp >> 2, wn = warp & 3;
    CFrag acc[4][2];
#pragma unroll
    for (int mi = 0; mi < 4; mi++)
#pragma unroll
        for (int ni = 0; ni < 2; ni++) wmma::fill_fragment(acc[mi][ni], 0.0f);

    const __nv_bfloat16* Agh = g_Ph + (size_t)h * SEQ * SEQ + (size_t)i0 * SEQ;
    const __nv_bfloat16* Agl = g_Pl + (size_t)h * SEQ * SEQ + (size_t)i0 * SEQ;
    const __nv_bfloat16* Bgh = g_qh[z] + VOFF + h * DHEAD;
    const __nv_bfloat16* Bgl = g_ql[z] + VOFF + h * DHEAD;

    auto issue = [&](int p) {
        uint32_t s = sb + (p % 3) * BUF_NN;
        cpA(s,          Agh + p * BK, SEQ);
        cpA(s + 12288,  Agl + p * BK, SEQ);
        cpB(s + 24576,  Bgh + (size_t)p * BK * QKVO, QKVO);
        cpB(s + 33792,  Bgl + (size_t)p * BK * QKVO, QKVO);
        CP_COMMIT();
    };
    int ktiles = (i0 + 128) / BK;  // >= 4
    issue(0);
    issue(1);
    for (int kt = 0; kt < ktiles; ++kt) {
        if (kt + 1 < ktiles) CP_WAIT1(); else CP_WAIT0();
        __syncthreads();
        const __nv_bfloat16* s = reinterpret_cast<const __nv_bfloat16*>(smc + (kt % 3) * BUF_NN);
        mma_bf16<false>(s, s + ASZ, s + 2 * ASZ, s + 2 * ASZ + BSZ, acc, wm, wn);
        if (kt + 2 < ktiles) issue(kt + 2);
    }
    epi_direct(acc, g_attn[z] + (size_t)i0 * HIDN + h * DHEAD, HIDN, wm, wn);
}

// ---------------- kernel 6: output projections (128x256, 3-stage, 1 sync/tile) ----------------
__global__ void __launch_bounds__(256)
k_out(float* __restrict__ out) {
    int z = blockIdx.z;
    int i0 = blockIdx.y * 128, n0 = blockIdx.x * 256;
    extern __shared__ __align__(128) char smc[];
    uint32_t sb = smem_to_u32(smc);
    int warp = threadIdx.x >> 5, wm = warp >> 2, wn = warp & 3;
    CFrag acc[4][4];
#pragma unroll
    for (int mi = 0; mi < 4; mi++)
#pragma unroll
        for (int ni = 0; ni < 4; ni++) wmma::fill_fragment(acc[mi][ni], 0.0f);

    const __nv_bfloat16* Agh = g_ah[z] + (size_t)i0 * HIDN;
    const __nv_bfloat16* Agl = g_al[z] + (size_t)i0 * HIDN;
    const __nv_bfloat16* Bgh = g_Woh[z] + n0;
    const __nv_bfloat16* Bgl = g_Wol[z] + n0;

    auto issue = [&](int p) {
        uint32_t s = sb + (p % 3) * BUF_W;
        cpA(s,            Agh + p * BK, HIDN);
        cpA(s + 12288,    Agl + p * BK, HIDN);
        cpB256(s + 24576, Bgh + (size_t)p * BK * HIDN, HIDN);
        cpB256(s + 41984, Bgl + (size_t)p * BK * HIDN, HIDN);
        CP_COMMIT();
    };
    const int kts = HIDN / BK;  // 64
    issue(0);
    issue(1);
    for (int kt = 0; kt < kts; ++kt) {
        if (kt + 1 < kts) CP_WAIT1(); else CP_WAIT0();
        __syncthreads();
        const __nv_bfloat16* s = reinterpret_cast<const __nv_bfloat16*>(smc + (kt % 3) * BUF_W);
        mma_w(s, s + ASZ, s + 2 * ASZ, s + 2 * ASZ + B2SZ, acc, wm, wn);
        if (kt + 2 < kts) issue(kt + 2);
    }
    epi_w(acc, out + (size_t)z * SEQ * HIDN + (size_t)i0 * HIDN + n0, HIDN, wm, wn);
}

// ---------------- launch ----------------
extern "C" void kernel_launch(void* const* d_in, const int* in_sizes, int n_in,
                              void* d_out, int out_size) {
    const float* hidden = (const float*)d_in[0];
    const int*   pos    = (const int*)d_in[1];
    const float* Wqkv_r = (const float*)d_in[2];
    const float* bqkv_r = (const float*)d_in[3];
    const float* Wqkv_i = (const float*)d_in[4];
    const float* bqkv_i = (const float*)d_in[5];
    const float* Wo_r   = (const float*)d_in[6];
    const float* Wo_i   = (const float*)d_in[7];
    float* out = (float*)d_out;

    cudaFuncSetAttribute(k_qkv,    cudaFuncAttributeMaxDynamicSharedMemorySize, SMEM_W);
    cudaFuncSetAttribute(k_scores, cudaFuncAttributeMaxDynamicSharedMemorySize, SMEM_NT);
    cudaFuncSetAttribute(k_av,     cudaFuncAttributeMaxDynamicSharedMemorySize, SMEM_NN);
    cudaFuncSetAttribute(k_out,    cudaFuncAttributeMaxDynamicSharedMemorySize, SMEM_W);

    dim3 blk(256);
    k_trig<<<(SEQ * DHEAD) / 256, blk>>>(pos);
    k_split<<<(SEQ * HIDN) / 1024, blk>>>(hidden, 0, SEQ * HIDN);
    k_split<<<(HIDN * QKVO) / 1024, blk>>>(Wqkv_r, 1, HIDN * QKVO);
    k_split<<<(HIDN * QKVO) / 1024, blk>>>(Wqkv_i, 2, HIDN * QKVO);
    k_split<<<(HIDN * HIDN) / 1024, blk>>>(Wo_r, 3, HIDN * HIDN);
    k_split<<<(HIDN * HIDN) / 1024, blk>>>(Wo_i, 4, HIDN * HIDN);
    k_qkv<<<dim3(QKVO / 256, SEQ / 128, 2), blk, SMEM_W>>>();
    k_biasrope<<<(SEQ * QKVO) / 256, blk>>>(bqkv_r, bqkv_i);
    k_scores<<<dim3(SEQ / 128, SEQ / 128, NHEAD), blk, SMEM_NT>>>();
    k_softmax<<<NHEAD * SEQ, blk>>>();
    k_av<<<dim3(1, SEQ / 128, NHEAD * 2), blk, SMEM_NN>>>();
    k_split<<<(2 * SEQ * HIDN) / 1024, blk>>>(nullptr, 5, 2 * SEQ * HIDN);
    int zcount = (out_size >= 2 * SEQ * HIDN) ? 2 : 1;
    k_out<<<dim3(HIDN / 256, SEQ / 128, zcount), blk, SMEM_W>>>(out);
}